// round 2
// baseline (speedup 1.0000x reference)
#include <cuda_runtime.h>
#include <cstdint>

#define NN 100000
#define EE 3200000
#define ET (EE + NN)           // 3,300,000 edges incl. self loops
#define HEADS 4
#define HD 64
#define D1 256                 // HEADS*HD
#define INDIM 128

// ---------------- scratch (static device globals; no allocs) ----------------
__device__ float g_h1[(size_t)NN * D1];     // layer1 h = x@W1            (102.4 MB)
__device__ float g_g1[(size_t)NN * D1];     // elu(agg1 + b1), layer2 in  (102.4 MB)
__device__ float g_h2[(size_t)NN * HD];     // layer2 h = g1@W2           (25.6 MB)
__device__ float g_as1[NN * HEADS];
__device__ float g_ad1[NN * HEADS];
__device__ float g_as2[NN];
__device__ float g_ad2[NN];
__device__ int   g_deg[NN];
__device__ int   g_rowptr[NN + 1];
__device__ int   g_cursor[NN];
__device__ int   g_blksums[256];
__device__ int   g_srcs[ET];                // CSR-by-dst src indices (13.2 MB)

__device__ __forceinline__ float lrelu(float x) { return fmaxf(x, 0.2f * x); }
__device__ __forceinline__ float eluf(float x)  { return x > 0.f ? x : expm1f(x); }

// ---------------- SGEMM: BM=128, BK=8, TM=8; BN/TN template ----------------
template<int BN, int TN>
__device__ __forceinline__ void sgemm_body(const float* __restrict__ A,
                                           const float* __restrict__ B,
                                           float* __restrict__ C,
                                           int M, int N, int K) {
    constexpr int BM = 128, BK = 8, TM = 8;
    __shared__ float As[BK][BM];
    __shared__ float Bs[BK][BN];

    const int tid = threadIdx.x;                 // 256 threads
    const int tx  = tid % (BN / TN);
    const int ty  = tid / (BN / TN);
    const int rowBase = blockIdx.y * BM;
    const int colBase = blockIdx.x * BN;

    // A tile load mapping: 128x8 floats = 1024 -> 4/thread (one float4 along K)
    const int ar = tid >> 1;
    const int ak = (tid & 1) << 2;
    // B tile load mapping: BK x BN floats -> float4 along N
    constexpr int B4 = BK * BN / 4;
    const int br = tid / (BN / 4);
    const int bc = (tid % (BN / 4)) * 4;

    float acc[TM][TN];
#pragma unroll
    for (int i = 0; i < TM; i++)
#pragma unroll
        for (int j = 0; j < TN; j++) acc[i][j] = 0.f;

    for (int k0 = 0; k0 < K; k0 += BK) {
        // load A (guard M)
        {
            int row = rowBase + ar;
            float4 a4 = make_float4(0.f, 0.f, 0.f, 0.f);
            if (row < M) a4 = *(const float4*)(A + (size_t)row * K + k0 + ak);
            As[ak + 0][ar] = a4.x;
            As[ak + 1][ar] = a4.y;
            As[ak + 2][ar] = a4.z;
            As[ak + 3][ar] = a4.w;
        }
        // load B (N, K exact multiples here)
        if (tid < B4) {
            float4 b4 = *(const float4*)(B + (size_t)(k0 + br) * N + colBase + bc);
            *(float4*)&Bs[br][bc] = b4;
        }
        __syncthreads();

#pragma unroll
        for (int k = 0; k < BK; k++) {
            float a_reg[TM], b_reg[TN];
            float4 av0 = *(const float4*)&As[k][ty * TM];
            float4 av1 = *(const float4*)&As[k][ty * TM + 4];
            a_reg[0]=av0.x; a_reg[1]=av0.y; a_reg[2]=av0.z; a_reg[3]=av0.w;
            a_reg[4]=av1.x; a_reg[5]=av1.y; a_reg[6]=av1.z; a_reg[7]=av1.w;
#pragma unroll
            for (int j = 0; j < TN; j += 4) {
                float4 bv = *(const float4*)&Bs[k][tx * TN + j];
                b_reg[j+0]=bv.x; b_reg[j+1]=bv.y; b_reg[j+2]=bv.z; b_reg[j+3]=bv.w;
            }
#pragma unroll
            for (int i = 0; i < TM; i++)
#pragma unroll
                for (int j = 0; j < TN; j++)
                    acc[i][j] = fmaf(a_reg[i], b_reg[j], acc[i][j]);
        }
        __syncthreads();
    }

#pragma unroll
    for (int i = 0; i < TM; i++) {
        int row = rowBase + ty * TM + i;
        if (row < M) {
#pragma unroll
            for (int j = 0; j < TN; j += 4) {
                float4 o = make_float4(acc[i][j], acc[i][j+1], acc[i][j+2], acc[i][j+3]);
                *(float4*)(C + (size_t)row * N + colBase + tx * TN + j) = o;
            }
        }
    }
}

__global__ void k_gemm1(const float* __restrict__ A, const float* __restrict__ B) {
    sgemm_body<128, 8>(A, B, g_h1, NN, D1, INDIM);
}
__global__ void k_gemm2(const float* __restrict__ B) {
    sgemm_body<64, 4>(g_g1, B, g_h2, NN, HD, D1);
}

// ---------------- attention coefficient dots ----------------
__global__ void k_alpha1(const float* __restrict__ a_src1, const float* __restrict__ a_dst1) {
    int t = blockIdx.x * blockDim.x + threadIdx.x;
    if (t >= NN * HEADS) return;
    int n = t >> 2, h = t & 3;
    const float4* hp = (const float4*)(g_h1 + (size_t)n * D1 + h * HD);
    const float4* sp = (const float4*)(a_src1 + h * HD);
    const float4* dp = (const float4*)(a_dst1 + h * HD);
    float ss = 0.f, dd = 0.f;
#pragma unroll
    for (int i = 0; i < HD / 4; i++) {
        float4 hv = hp[i], sv = sp[i], dv = dp[i];
        ss += hv.x * sv.x + hv.y * sv.y + hv.z * sv.z + hv.w * sv.w;
        dd += hv.x * dv.x + hv.y * dv.y + hv.z * dv.z + hv.w * dv.w;
    }
    g_as1[t] = ss;
    g_ad1[t] = dd;
}

__global__ void k_alpha2(const float* __restrict__ a_src2, const float* __restrict__ a_dst2) {
    int n = blockIdx.x * blockDim.x + threadIdx.x;
    if (n >= NN) return;
    const float4* hp = (const float4*)(g_h2 + (size_t)n * HD);
    const float4* sp = (const float4*)a_src2;
    const float4* dp = (const float4*)a_dst2;
    float ss = 0.f, dd = 0.f;
#pragma unroll
    for (int i = 0; i < HD / 4; i++) {
        float4 hv = hp[i], sv = sp[i], dv = dp[i];
        ss += hv.x * sv.x + hv.y * sv.y + hv.z * sv.z + hv.w * sv.w;
        dd += hv.x * dv.x + hv.y * dv.y + hv.z * dv.z + hv.w * dv.w;
    }
    g_as2[n] = ss;
    g_ad2[n] = dd;
}

// ---------------- CSR build (counting sort by dst) ----------------
__global__ void k_deg_init() {
    int i = blockIdx.x * blockDim.x + threadIdx.x;
    if (i < NN) g_deg[i] = 1;   // self-loop pre-counted
}
__global__ void k_hist(const int* __restrict__ dst) {
    int i = blockIdx.x * blockDim.x + threadIdx.x;
    if (i < EE) atomicAdd(&g_deg[dst[i]], 1);
}

#define SCAN_B 512
#define SCAN_NB ((NN + SCAN_B - 1) / SCAN_B)   // 196

__global__ void k_scan1() {
    __shared__ int sm[SCAN_B];
    int i = blockIdx.x * SCAN_B + threadIdx.x;
    int v = (i < NN) ? g_deg[i] : 0;
    sm[threadIdx.x] = v;
    __syncthreads();
    for (int off = 1; off < SCAN_B; off <<= 1) {
        int t = (threadIdx.x >= off) ? sm[threadIdx.x - off] : 0;
        __syncthreads();
        sm[threadIdx.x] += t;
        __syncthreads();
    }
    if (i < NN) g_rowptr[i] = sm[threadIdx.x] - v;   // exclusive within block
    if (threadIdx.x == SCAN_B - 1) g_blksums[blockIdx.x] = sm[threadIdx.x];
}
__global__ void k_scan2() {
    __shared__ int sm[256];
    int v = (threadIdx.x < SCAN_NB) ? g_blksums[threadIdx.x] : 0;
    sm[threadIdx.x] = v;
    __syncthreads();
    for (int off = 1; off < 256; off <<= 1) {
        int t = (threadIdx.x >= off) ? sm[threadIdx.x - off] : 0;
        __syncthreads();
        sm[threadIdx.x] += t;
        __syncthreads();
    }
    g_blksums[threadIdx.x] = sm[threadIdx.x] - v;    // exclusive
}
__global__ void k_scan3() {
    int i = blockIdx.x * blockDim.x + threadIdx.x;
    if (i < NN) {
        int r = g_rowptr[i] + g_blksums[i / SCAN_B];
        g_rowptr[i] = r;
        g_cursor[i] = r;
    } else if (i == NN) {
        g_rowptr[NN] = ET;
    }
}
__global__ void k_scatter(const int* __restrict__ ei) {
    int i = blockIdx.x * blockDim.x + threadIdx.x;
    if (i >= ET) return;
    int s, d;
    if (i < EE) { s = ei[i]; d = ei[EE + i]; }
    else        { s = d = i - EE; }
    int pos = atomicAdd(&g_cursor[d], 1);
    g_srcs[pos] = s;
}

// ---------------- layer-1 aggregation: one warp per dst node ----------------
__global__ void k_agg1(const float* __restrict__ b1) {
    int gw = (blockIdx.x * blockDim.x + threadIdx.x) >> 5;
    if (gw >= NN) return;
    const int lane = threadIdx.x & 31;
    const int v = gw;
    const int r0 = g_rowptr[v], r1 = g_rowptr[v + 1];
    const float4 adv = ((const float4*)g_ad1)[v];

    // pass 1: per-head max over incident edges
    float mx0 = -1e30f, mx1 = -1e30f, mx2 = -1e30f, mx3 = -1e30f;
    for (int e = r0 + lane; e < r1; e += 32) {
        int s = g_srcs[e];
        float4 as = ((const float4*)g_as1)[s];
        mx0 = fmaxf(mx0, lrelu(as.x + adv.x));
        mx1 = fmaxf(mx1, lrelu(as.y + adv.y));
        mx2 = fmaxf(mx2, lrelu(as.z + adv.z));
        mx3 = fmaxf(mx3, lrelu(as.w + adv.w));
    }
#pragma unroll
    for (int o = 16; o; o >>= 1) {
        mx0 = fmaxf(mx0, __shfl_xor_sync(0xffffffffu, mx0, o));
        mx1 = fmaxf(mx1, __shfl_xor_sync(0xffffffffu, mx1, o));
        mx2 = fmaxf(mx2, __shfl_xor_sync(0xffffffffu, mx2, o));
        mx3 = fmaxf(mx3, __shfl_xor_sync(0xffffffffu, mx3, o));
    }

    // pass 2: per-head softmax denominator
    float s0 = 0.f, s1 = 0.f, s2 = 0.f, s3 = 0.f;
    for (int e = r0 + lane; e < r1; e += 32) {
        int s = g_srcs[e];
        float4 as = ((const float4*)g_as1)[s];
        s0 += __expf(lrelu(as.x + adv.x) - mx0);
        s1 += __expf(lrelu(as.y + adv.y) - mx1);
        s2 += __expf(lrelu(as.z + adv.z) - mx2);
        s3 += __expf(lrelu(as.w + adv.w) - mx3);
    }
#pragma unroll
    for (int o = 16; o; o >>= 1) {
        s0 += __shfl_xor_sync(0xffffffffu, s0, o);
        s1 += __shfl_xor_sync(0xffffffffu, s1, o);
        s2 += __shfl_xor_sync(0xffffffffu, s2, o);
        s3 += __shfl_xor_sync(0xffffffffu, s3, o);
    }
    const float i0 = 1.f / s0, i1 = 1.f / s1, i2 = 1.f / s2, i3 = 1.f / s3;

    // pass 3: weighted aggregation. lane owns elems [4*lane,4*lane+4) (heads 0/1)
    // and [128+4*lane, ...) (heads 2/3).
    const int hA = lane >> 4;                       // 0 or 1
    const float adA = hA ? adv.y : adv.x;
    const float adB = hA ? adv.w : adv.z;
    const float mA  = hA ? mx1 : mx0;
    const float mB  = hA ? mx3 : mx2;
    const float iA  = hA ? i1 : i0;
    const float iB  = hA ? i3 : i2;

    float4 acc0 = make_float4(0.f, 0.f, 0.f, 0.f);
    float4 acc1 = make_float4(0.f, 0.f, 0.f, 0.f);
    int s = (r0 < r1) ? g_srcs[r0] : 0;
    for (int e = r0; e < r1; e++) {
        int snext = (e + 1 < r1) ? g_srcs[e + 1] : 0;
        float aA = __expf(lrelu(g_as1[s * 4 + hA]     + adA) - mA) * iA;
        float aB = __expf(lrelu(g_as1[s * 4 + 2 + hA] + adB) - mB) * iB;
        const float4* hp = (const float4*)(g_h1 + (size_t)s * D1);
        float4 x0 = hp[lane];
        float4 x1 = hp[lane + 32];
        acc0.x = fmaf(x0.x, aA, acc0.x);
        acc0.y = fmaf(x0.y, aA, acc0.y);
        acc0.z = fmaf(x0.z, aA, acc0.z);
        acc0.w = fmaf(x0.w, aA, acc0.w);
        acc1.x = fmaf(x1.x, aB, acc1.x);
        acc1.y = fmaf(x1.y, aB, acc1.y);
        acc1.z = fmaf(x1.z, aB, acc1.z);
        acc1.w = fmaf(x1.w, aB, acc1.w);
        s = snext;
    }

    // epilogue: +b1, ELU, store as layer-2 input
    float4 bb0 = ((const float4*)b1)[lane];
    float4 bb1 = ((const float4*)b1)[lane + 32];
    float4 o0, o1;
    o0.x = eluf(acc0.x + bb0.x); o0.y = eluf(acc0.y + bb0.y);
    o0.z = eluf(acc0.z + bb0.z); o0.w = eluf(acc0.w + bb0.w);
    o1.x = eluf(acc1.x + bb1.x); o1.y = eluf(acc1.y + bb1.y);
    o1.z = eluf(acc1.z + bb1.z); o1.w = eluf(acc1.w + bb1.w);
    float4* op = (float4*)(g_g1 + (size_t)v * D1);
    op[lane]      = o0;
    op[lane + 32] = o1;
}

// ---------------- layer-2 aggregation + ELU + final linear ----------------
__global__ void k_agg2(const float* __restrict__ b2, const float* __restrict__ lw,
                       const float* __restrict__ lb, float* __restrict__ out) {
    int gw = (blockIdx.x * blockDim.x + threadIdx.x) >> 5;
    if (gw >= NN) return;
    const int lane = threadIdx.x & 31;
    const int v = gw;
    const int r0 = g_rowptr[v], r1 = g_rowptr[v + 1];
    const float adv = g_ad2[v];

    float mx = -1e30f;
    for (int e = r0 + lane; e < r1; e += 32)
        mx = fmaxf(mx, lrelu(g_as2[g_srcs[e]] + adv));
#pragma unroll
    for (int o = 16; o; o >>= 1) mx = fmaxf(mx, __shfl_xor_sync(0xffffffffu, mx, o));

    float sm = 0.f;
    for (int e = r0 + lane; e < r1; e += 32)
        sm += __expf(lrelu(g_as2[g_srcs[e]] + adv) - mx);
#pragma unroll
    for (int o = 16; o; o >>= 1) sm += __shfl_xor_sync(0xffffffffu, sm, o);
    const float inv = 1.f / sm;

    float2 acc = make_float2(0.f, 0.f);
    int s = (r0 < r1) ? g_srcs[r0] : 0;
    for (int e = r0; e < r1; e++) {
        int snext = (e + 1 < r1) ? g_srcs[e + 1] : 0;
        float a = __expf(lrelu(g_as2[s] + adv) - mx) * inv;
        float2 x = ((const float2*)(g_h2 + (size_t)s * HD))[lane];
        acc.x = fmaf(x.x, a, acc.x);
        acc.y = fmaf(x.y, a, acc.y);
        s = snext;
    }

    const int d = 2 * lane;
    float t0 = eluf(acc.x + b2[d]);
    float t1 = eluf(acc.y + b2[d + 1]);
    float y0 = t0 * lw[d * 2]     + t1 * lw[d * 2 + 2];
    float y1 = t0 * lw[d * 2 + 1] + t1 * lw[d * 2 + 3];
#pragma unroll
    for (int o = 16; o; o >>= 1) {
        y0 += __shfl_xor_sync(0xffffffffu, y0, o);
        y1 += __shfl_xor_sync(0xffffffffu, y1, o);
    }
    if (lane == 0) {
        out[2 * v]     = y0 + lb[0];
        out[2 * v + 1] = y1 + lb[1];
    }
}

// ---------------- launch ----------------
extern "C" void kernel_launch(void* const* d_in, const int* in_sizes, int n_in,
                              void* d_out, int out_size) {
    const float* x      = (const float*)d_in[0];
    const int*   ei     = (const int*)d_in[1];     // int32: jax default x64 disabled
    const float* W1     = (const float*)d_in[2];
    const float* a_src1 = (const float*)d_in[3];
    const float* a_dst1 = (const float*)d_in[4];
    const float* b1     = (const float*)d_in[5];
    const float* W2     = (const float*)d_in[6];
    const float* a_src2 = (const float*)d_in[7];
    const float* a_dst2 = (const float*)d_in[8];
    const float* b2     = (const float*)d_in[9];
    const float* lw     = (const float*)d_in[10];
    const float* lb     = (const float*)d_in[11];
    float*       out    = (float*)d_out;

    // CSR build (independent of GEMM1)
    k_deg_init<<<(NN + 255) / 256, 256>>>();
    k_hist<<<(EE + 255) / 256, 256>>>(ei + EE);
    k_scan1<<<SCAN_NB, SCAN_B>>>();
    k_scan2<<<1, 256>>>();
    k_scan3<<<(NN + 1 + 255) / 256, 256>>>();
    k_scatter<<<(ET + 255) / 256, 256>>>(ei);

    // layer 1
    k_gemm1<<<dim3(2, (NN + 127) / 128), 256>>>(x, W1);
    k_alpha1<<<(NN * HEADS + 255) / 256, 256>>>(a_src1, a_dst1);
    k_agg1<<<(NN + 7) / 8, 256>>>(b1);

    // layer 2
    k_gemm2<<<dim3(1, (NN + 127) / 128), 256>>>(W2);
    k_alpha2<<<(NN + 255) / 256, 256>>>(a_src2, a_dst2);
    k_agg2<<<(NN + 7) / 8, 256>>>(b2, lw, lb, out);
}

// round 3
// speedup vs baseline: 1.1964x; 1.1964x over previous
#include <cuda_runtime.h>
#include <cstdint>

#define NN 100000
#define EE 3200000
#define ET (EE + NN)           // 3,300,000 edges incl. self loops
#define HEADS 4
#define HD 64
#define D1 256                 // HEADS*HD
#define INDIM 128

// ---------------- scratch (static device globals; no allocs) ----------------
__device__ float g_h1[(size_t)NN * D1];     // layer1 h = x@W1            (102.4 MB)
__device__ float g_g1[(size_t)NN * D1];     // elu(agg1 + b1), layer2 in  (102.4 MB)
__device__ float g_h2[(size_t)NN * HD];     // layer2 h = g1@W2           (25.6 MB)
__device__ float g_as1[NN * HEADS];
__device__ float g_ad1[NN * HEADS];
__device__ float g_as2[NN];
__device__ float g_ad2[NN];
__device__ int   g_deg[NN];
__device__ int   g_rowptr[NN + 1];
__device__ int   g_cursor[NN];
__device__ int   g_blksums[256];
__device__ int   g_srcs[ET];                // CSR-by-dst src indices (13.2 MB)

__device__ __forceinline__ float lrelu(float x) { return fmaxf(x, 0.2f * x); }
__device__ __forceinline__ float eluf(float x)  { return x > 0.f ? x : expm1f(x); }

__device__ __forceinline__ unsigned f2tf32(float f) {
    unsigned u;
    asm("cvt.rna.tf32.f32 %0, %1;" : "=r"(u) : "f"(f));
    return u;
}

__device__ __forceinline__ void mma_tf32(float* d, const unsigned* a, const unsigned* b) {
    asm volatile(
        "mma.sync.aligned.m16n8k8.row.col.f32.tf32.tf32.f32 "
        "{%0,%1,%2,%3}, {%4,%5,%6,%7}, {%8,%9}, {%0,%1,%2,%3};\n"
        : "+f"(d[0]), "+f"(d[1]), "+f"(d[2]), "+f"(d[3])
        : "r"(a[0]), "r"(a[1]), "r"(a[2]), "r"(a[3]), "r"(b[0]), "r"(b[1]));
}

// ---------------- tf32 tensor-core GEMM: BM=128, BN=64, BK=16 ----------------
// 8 warps: warp grid 4(m) x 2(n); each warp 32x32 = 2 m-tiles x 4 n-tiles of m16n8k8.
// smem padded so all fragment loads are bank-conflict-free.
template<int N, int K>
__device__ __forceinline__ void mma_gemm(const float* __restrict__ A,
                                         const float* __restrict__ Bg,
                                         float* __restrict__ C, int M) {
    constexpr int BM = 128, BN = 64, BK = 16;
    constexpr int ASTR = 20;   // BK+4 floats: bank(20r+c) covers 0..31
    constexpr int BSTR = 72;   // BN+8 floats: bank(8c+r) covers 0..31
    constexpr int NT = K / BK;
    __shared__ unsigned As[2][BM * ASTR];
    __shared__ unsigned Bs[2][BK * BSTR];

    const int tid  = threadIdx.x;
    const int lane = tid & 31, wid = tid >> 5;
    const int wm = wid & 3, wn = wid >> 2;
    const int r = lane >> 2, cq = lane & 3;
    const int row0 = blockIdx.y * BM;
    const int col0 = blockIdx.x * BN;

    // gmem staging: A tile 128x16 = 512 float4 (2/thread); B tile 16x64 = 256 float4
    const int ar0 = tid >> 2,          ak0 = (tid & 3) << 2;
    const int ar1 = (tid + 256) >> 2,  ak1 = (tid & 3) << 2;
    const int bkr = tid >> 4,          bnc = (tid & 15) << 2;

    float4 aR0, aR1, bR;

    float acc[2][4][4];
#pragma unroll
    for (int mt = 0; mt < 2; mt++)
#pragma unroll
        for (int nt = 0; nt < 4; nt++)
#pragma unroll
            for (int i = 0; i < 4; i++) acc[mt][nt][i] = 0.f;

    // prologue: tile 0
    {
        aR0 = make_float4(0.f, 0.f, 0.f, 0.f);
        aR1 = make_float4(0.f, 0.f, 0.f, 0.f);
        if (row0 + ar0 < M) aR0 = *(const float4*)(A + (size_t)(row0 + ar0) * K + ak0);
        if (row0 + ar1 < M) aR1 = *(const float4*)(A + (size_t)(row0 + ar1) * K + ak1);
        bR = *(const float4*)(Bg + (size_t)bkr * N + col0 + bnc);
        *(uint4*)&As[0][ar0 * ASTR + ak0] =
            make_uint4(f2tf32(aR0.x), f2tf32(aR0.y), f2tf32(aR0.z), f2tf32(aR0.w));
        *(uint4*)&As[0][ar1 * ASTR + ak1] =
            make_uint4(f2tf32(aR1.x), f2tf32(aR1.y), f2tf32(aR1.z), f2tf32(aR1.w));
        *(uint4*)&Bs[0][bkr * BSTR + bnc] =
            make_uint4(f2tf32(bR.x), f2tf32(bR.y), f2tf32(bR.z), f2tf32(bR.w));
    }
    __syncthreads();

#pragma unroll 1
    for (int it = 0; it < NT; it++) {
        const int buf = it & 1;
        if (it + 1 < NT) {
            const int k0 = (it + 1) * BK;
            aR0 = make_float4(0.f, 0.f, 0.f, 0.f);
            aR1 = make_float4(0.f, 0.f, 0.f, 0.f);
            if (row0 + ar0 < M) aR0 = *(const float4*)(A + (size_t)(row0 + ar0) * K + k0 + ak0);
            if (row0 + ar1 < M) aR1 = *(const float4*)(A + (size_t)(row0 + ar1) * K + k0 + ak1);
            bR = *(const float4*)(Bg + (size_t)(k0 + bkr) * N + col0 + bnc);
        }

#pragma unroll
        for (int kt = 0; kt < 2; kt++) {
            unsigned a[2][4], b[4][2];
#pragma unroll
            for (int mt = 0; mt < 2; mt++) {
                const int mb = wm * 32 + mt * 16;
                const unsigned* ap = &As[buf][0];
                a[mt][0] = ap[(mb + r) * ASTR + kt * 8 + cq];
                a[mt][1] = ap[(mb + r + 8) * ASTR + kt * 8 + cq];
                a[mt][2] = ap[(mb + r) * ASTR + kt * 8 + cq + 4];
                a[mt][3] = ap[(mb + r + 8) * ASTR + kt * 8 + cq + 4];
            }
#pragma unroll
            for (int nt = 0; nt < 4; nt++) {
                const int nb = wn * 32 + nt * 8 + r;
                b[nt][0] = Bs[buf][(kt * 8 + cq) * BSTR + nb];
                b[nt][1] = Bs[buf][(kt * 8 + cq + 4) * BSTR + nb];
            }
#pragma unroll
            for (int mt = 0; mt < 2; mt++)
#pragma unroll
                for (int nt = 0; nt < 4; nt++)
                    mma_tf32(acc[mt][nt], a[mt], b[nt]);
        }

        if (it + 1 < NT) {
            const int nb = buf ^ 1;
            *(uint4*)&As[nb][ar0 * ASTR + ak0] =
                make_uint4(f2tf32(aR0.x), f2tf32(aR0.y), f2tf32(aR0.z), f2tf32(aR0.w));
            *(uint4*)&As[nb][ar1 * ASTR + ak1] =
                make_uint4(f2tf32(aR1.x), f2tf32(aR1.y), f2tf32(aR1.z), f2tf32(aR1.w));
            *(uint4*)&Bs[nb][bkr * BSTR + bnc] =
                make_uint4(f2tf32(bR.x), f2tf32(bR.y), f2tf32(bR.z), f2tf32(bR.w));
        }
        __syncthreads();
    }

    // epilogue
#pragma unroll
    for (int mt = 0; mt < 2; mt++) {
        const int m_lo = row0 + wm * 32 + mt * 16 + r;
        const int m_hi = m_lo + 8;
#pragma unroll
        for (int nt = 0; nt < 4; nt++) {
            const int n = col0 + wn * 32 + nt * 8 + cq * 2;
            if (m_lo < M)
                *(float2*)(C + (size_t)m_lo * N + n) = make_float2(acc[mt][nt][0], acc[mt][nt][1]);
            if (m_hi < M)
                *(float2*)(C + (size_t)m_hi * N + n) = make_float2(acc[mt][nt][2], acc[mt][nt][3]);
        }
    }
}

__global__ void __launch_bounds__(256) k_gemm1(const float* __restrict__ A,
                                               const float* __restrict__ B) {
    mma_gemm<D1, INDIM>(A, B, g_h1, NN);
}
__global__ void __launch_bounds__(256) k_gemm2(const float* __restrict__ B) {
    mma_gemm<HD, D1>(g_g1, B, g_h2, NN);
}

// ---------------- attention coefficient dots ----------------
__global__ void k_alpha1(const float* __restrict__ a_src1, const float* __restrict__ a_dst1) {
    int t = blockIdx.x * blockDim.x + threadIdx.x;
    if (t >= NN * HEADS) return;
    int n = t >> 2, h = t & 3;
    const float4* hp = (const float4*)(g_h1 + (size_t)n * D1 + h * HD);
    const float4* sp = (const float4*)(a_src1 + h * HD);
    const float4* dp = (const float4*)(a_dst1 + h * HD);
    float ss = 0.f, dd = 0.f;
#pragma unroll
    for (int i = 0; i < HD / 4; i++) {
        float4 hv = hp[i], sv = sp[i], dv = dp[i];
        ss += hv.x * sv.x + hv.y * sv.y + hv.z * sv.z + hv.w * sv.w;
        dd += hv.x * dv.x + hv.y * dv.y + hv.z * dv.z + hv.w * dv.w;
    }
    g_as1[t] = ss;
    g_ad1[t] = dd;
}

__global__ void k_alpha2(const float* __restrict__ a_src2, const float* __restrict__ a_dst2) {
    int n = blockIdx.x * blockDim.x + threadIdx.x;
    if (n >= NN) return;
    const float4* hp = (const float4*)(g_h2 + (size_t)n * HD);
    const float4* sp = (const float4*)a_src2;
    const float4* dp = (const float4*)a_dst2;
    float ss = 0.f, dd = 0.f;
#pragma unroll
    for (int i = 0; i < HD / 4; i++) {
        float4 hv = hp[i], sv = sp[i], dv = dp[i];
        ss += hv.x * sv.x + hv.y * sv.y + hv.z * sv.z + hv.w * sv.w;
        dd += hv.x * dv.x + hv.y * dv.y + hv.z * dv.z + hv.w * dv.w;
    }
    g_as2[n] = ss;
    g_ad2[n] = dd;
}

// ---------------- CSR build (counting sort by dst) ----------------
__global__ void k_deg_init() {
    int i = blockIdx.x * blockDim.x + threadIdx.x;
    if (i < NN) g_deg[i] = 1;   // self-loop pre-counted
}
__global__ void k_hist(const int* __restrict__ dst) {
    int i = blockIdx.x * blockDim.x + threadIdx.x;
    if (i < EE) atomicAdd(&g_deg[dst[i]], 1);
}

#define SCAN_B 512
#define SCAN_NB ((NN + SCAN_B - 1) / SCAN_B)   // 196

__global__ void k_scan1() {
    __shared__ int sm[SCAN_B];
    int i = blockIdx.x * SCAN_B + threadIdx.x;
    int v = (i < NN) ? g_deg[i] : 0;
    sm[threadIdx.x] = v;
    __syncthreads();
    for (int off = 1; off < SCAN_B; off <<= 1) {
        int t = (threadIdx.x >= off) ? sm[threadIdx.x - off] : 0;
        __syncthreads();
        sm[threadIdx.x] += t;
        __syncthreads();
    }
    if (i < NN) g_rowptr[i] = sm[threadIdx.x] - v;   // exclusive within block
    if (threadIdx.x == SCAN_B - 1) g_blksums[blockIdx.x] = sm[threadIdx.x];
}
__global__ void k_scan2() {
    __shared__ int sm[256];
    int v = (threadIdx.x < SCAN_NB) ? g_blksums[threadIdx.x] : 0;
    sm[threadIdx.x] = v;
    __syncthreads();
    for (int off = 1; off < 256; off <<= 1) {
        int t = (threadIdx.x >= off) ? sm[threadIdx.x - off] : 0;
        __syncthreads();
        sm[threadIdx.x] += t;
        __syncthreads();
    }
    g_blksums[threadIdx.x] = sm[threadIdx.x] - v;    // exclusive
}
__global__ void k_scan3() {
    int i = blockIdx.x * blockDim.x + threadIdx.x;
    if (i < NN) {
        int r = g_rowptr[i] + g_blksums[i / SCAN_B];
        g_rowptr[i] = r;
        g_cursor[i] = r;
    } else if (i == NN) {
        g_rowptr[NN] = ET;
    }
}
__global__ void k_scatter(const int* __restrict__ ei) {
    int i = blockIdx.x * blockDim.x + threadIdx.x;
    if (i >= ET) return;
    int s, d;
    if (i < EE) { s = ei[i]; d = ei[EE + i]; }
    else        { s = d = i - EE; }
    int pos = atomicAdd(&g_cursor[d], 1);
    g_srcs[pos] = s;
}

// ---------------- layer-1 aggregation: one warp per dst node ----------------
__global__ void k_agg1(const float* __restrict__ b1) {
    int gw = (blockIdx.x * blockDim.x + threadIdx.x) >> 5;
    if (gw >= NN) return;
    const int lane = threadIdx.x & 31;
    const int v = gw;
    const int r0 = g_rowptr[v], r1 = g_rowptr[v + 1];
    const float4 adv = ((const float4*)g_ad1)[v];

    // pass 1: per-head max over incident edges
    float mx0 = -1e30f, mx1 = -1e30f, mx2 = -1e30f, mx3 = -1e30f;
    for (int e = r0 + lane; e < r1; e += 32) {
        int s = g_srcs[e];
        float4 as = ((const float4*)g_as1)[s];
        mx0 = fmaxf(mx0, lrelu(as.x + adv.x));
        mx1 = fmaxf(mx1, lrelu(as.y + adv.y));
        mx2 = fmaxf(mx2, lrelu(as.z + adv.z));
        mx3 = fmaxf(mx3, lrelu(as.w + adv.w));
    }
#pragma unroll
    for (int o = 16; o; o >>= 1) {
        mx0 = fmaxf(mx0, __shfl_xor_sync(0xffffffffu, mx0, o));
        mx1 = fmaxf(mx1, __shfl_xor_sync(0xffffffffu, mx1, o));
        mx2 = fmaxf(mx2, __shfl_xor_sync(0xffffffffu, mx2, o));
        mx3 = fmaxf(mx3, __shfl_xor_sync(0xffffffffu, mx3, o));
    }

    // pass 2: per-head softmax denominator
    float s0 = 0.f, s1 = 0.f, s2 = 0.f, s3 = 0.f;
    for (int e = r0 + lane; e < r1; e += 32) {
        int s = g_srcs[e];
        float4 as = ((const float4*)g_as1)[s];
        s0 += __expf(lrelu(as.x + adv.x) - mx0);
        s1 += __expf(lrelu(as.y + adv.y) - mx1);
        s2 += __expf(lrelu(as.z + adv.z) - mx2);
        s3 += __expf(lrelu(as.w + adv.w) - mx3);
    }
#pragma unroll
    for (int o = 16; o; o >>= 1) {
        s0 += __shfl_xor_sync(0xffffffffu, s0, o);
        s1 += __shfl_xor_sync(0xffffffffu, s1, o);
        s2 += __shfl_xor_sync(0xffffffffu, s2, o);
        s3 += __shfl_xor_sync(0xffffffffu, s3, o);
    }
    const float i0 = 1.f / s0, i1 = 1.f / s1, i2 = 1.f / s2, i3 = 1.f / s3;

    // pass 3: weighted aggregation. lane owns elems [4*lane,4*lane+4) (heads 0/1)
    // and [128+4*lane, ...) (heads 2/3).
    const int hA = lane >> 4;                       // 0 or 1
    const float adA = hA ? adv.y : adv.x;
    const float adB = hA ? adv.w : adv.z;
    const float mA  = hA ? mx1 : mx0;
    const float mB  = hA ? mx3 : mx2;
    const float iA  = hA ? i1 : i0;
    const float iB  = hA ? i3 : i2;

    float4 acc0 = make_float4(0.f, 0.f, 0.f, 0.f);
    float4 acc1 = make_float4(0.f, 0.f, 0.f, 0.f);
    int s = (r0 < r1) ? g_srcs[r0] : 0;
    for (int e = r0; e < r1; e++) {
        int snext = (e + 1 < r1) ? g_srcs[e + 1] : 0;
        float aA = __expf(lrelu(g_as1[s * 4 + hA]     + adA) - mA) * iA;
        float aB = __expf(lrelu(g_as1[s * 4 + 2 + hA] + adB) - mB) * iB;
        const float4* hp = (const float4*)(g_h1 + (size_t)s * D1);
        float4 x0 = hp[lane];
        float4 x1 = hp[lane + 32];
        acc0.x = fmaf(x0.x, aA, acc0.x);
        acc0.y = fmaf(x0.y, aA, acc0.y);
        acc0.z = fmaf(x0.z, aA, acc0.z);
        acc0.w = fmaf(x0.w, aA, acc0.w);
        acc1.x = fmaf(x1.x, aB, acc1.x);
        acc1.y = fmaf(x1.y, aB, acc1.y);
        acc1.z = fmaf(x1.z, aB, acc1.z);
        acc1.w = fmaf(x1.w, aB, acc1.w);
        s = snext;
    }

    // epilogue: +b1, ELU, store as layer-2 input
    float4 bb0 = ((const float4*)b1)[lane];
    float4 bb1 = ((const float4*)b1)[lane + 32];
    float4 o0, o1;
    o0.x = eluf(acc0.x + bb0.x); o0.y = eluf(acc0.y + bb0.y);
    o0.z = eluf(acc0.z + bb0.z); o0.w = eluf(acc0.w + bb0.w);
    o1.x = eluf(acc1.x + bb1.x); o1.y = eluf(acc1.y + bb1.y);
    o1.z = eluf(acc1.z + bb1.z); o1.w = eluf(acc1.w + bb1.w);
    float4* op = (float4*)(g_g1 + (size_t)v * D1);
    op[lane]      = o0;
    op[lane + 32] = o1;
}

// ---------------- layer-2 aggregation + ELU + final linear ----------------
__global__ void k_agg2(const float* __restrict__ b2, const float* __restrict__ lw,
                       const float* __restrict__ lb, float* __restrict__ out) {
    int gw = (blockIdx.x * blockDim.x + threadIdx.x) >> 5;
    if (gw >= NN) return;
    const int lane = threadIdx.x & 31;
    const int v = gw;
    const int r0 = g_rowptr[v], r1 = g_rowptr[v + 1];
    const float adv = g_ad2[v];

    float mx = -1e30f;
    for (int e = r0 + lane; e < r1; e += 32)
        mx = fmaxf(mx, lrelu(g_as2[g_srcs[e]] + adv));
#pragma unroll
    for (int o = 16; o; o >>= 1) mx = fmaxf(mx, __shfl_xor_sync(0xffffffffu, mx, o));

    float sm = 0.f;
    for (int e = r0 + lane; e < r1; e += 32)
        sm += __expf(lrelu(g_as2[g_srcs[e]] + adv) - mx);
#pragma unroll
    for (int o = 16; o; o >>= 1) sm += __shfl_xor_sync(0xffffffffu, sm, o);
    const float inv = 1.f / sm;

    float2 acc = make_float2(0.f, 0.f);
    int s = (r0 < r1) ? g_srcs[r0] : 0;
    for (int e = r0; e < r1; e++) {
        int snext = (e + 1 < r1) ? g_srcs[e + 1] : 0;
        float a = __expf(lrelu(g_as2[s] + adv) - mx) * inv;
        float2 x = ((const float2*)(g_h2 + (size_t)s * HD))[lane];
        acc.x = fmaf(x.x, a, acc.x);
        acc.y = fmaf(x.y, a, acc.y);
        s = snext;
    }

    const int d = 2 * lane;
    float t0 = eluf(acc.x + b2[d]);
    float t1 = eluf(acc.y + b2[d + 1]);
    float y0 = t0 * lw[d * 2]     + t1 * lw[d * 2 + 2];
    float y1 = t0 * lw[d * 2 + 1] + t1 * lw[d * 2 + 3];
#pragma unroll
    for (int o = 16; o; o >>= 1) {
        y0 += __shfl_xor_sync(0xffffffffu, y0, o);
        y1 += __shfl_xor_sync(0xffffffffu, y1, o);
    }
    if (lane == 0) {
        out[2 * v]     = y0 + lb[0];
        out[2 * v + 1] = y1 + lb[1];
    }
}

// ---------------- launch ----------------
extern "C" void kernel_launch(void* const* d_in, const int* in_sizes, int n_in,
                              void* d_out, int out_size) {
    const float* x      = (const float*)d_in[0];
    const int*   ei     = (const int*)d_in[1];     // int32: jax default x64 disabled
    const float* W1     = (const float*)d_in[2];
    const float* a_src1 = (const float*)d_in[3];
    const float* a_dst1 = (const float*)d_in[4];
    const float* b1     = (const float*)d_in[5];
    const float* W2     = (const float*)d_in[6];
    const float* a_src2 = (const float*)d_in[7];
    const float* a_dst2 = (const float*)d_in[8];
    const float* b2     = (const float*)d_in[9];
    const float* lw     = (const float*)d_in[10];
    const float* lb     = (const float*)d_in[11];
    float*       out    = (float*)d_out;

    // CSR build (independent of GEMM1)
    k_deg_init<<<(NN + 255) / 256, 256>>>();
    k_hist<<<(EE + 255) / 256, 256>>>(ei + EE);
    k_scan1<<<SCAN_NB, SCAN_B>>>();
    k_scan2<<<1, 256>>>();
    k_scan3<<<(NN + 1 + 255) / 256, 256>>>();
    k_scatter<<<(ET + 255) / 256, 256>>>(ei);

    // layer 1
    k_gemm1<<<dim3(D1 / 64, (NN + 127) / 128), 256>>>(x, W1);
    k_alpha1<<<(NN * HEADS + 255) / 256, 256>>>(a_src1, a_dst1);
    k_agg1<<<(NN + 7) / 8, 256>>>(b1);

    // layer 2
    k_gemm2<<<dim3(1, (NN + 127) / 128), 256>>>(W2);
    k_alpha2<<<(NN + 255) / 256, 256>>>(a_src2, a_dst2);
    k_agg2<<<(NN + 7) / 8, 256>>>(b2, lw, lb, out);
}

// round 4
// speedup vs baseline: 1.2197x; 1.0194x over previous
#include <cuda_runtime.h>
#include <cstdint>

#define NN 100000
#define EE 3200000
#define ET (EE + NN)           // 3,300,000 edges incl. self loops
#define HEADS 4
#define HD 64
#define D1 256                 // HEADS*HD
#define INDIM 128

// ---------------- scratch (static device globals; no allocs) ----------------
__device__ float g_h1[(size_t)NN * D1];     // layer1 h = x@W1            (102.4 MB)
__device__ float g_g1[(size_t)NN * D1];     // elu(agg1 + b1), layer2 in  (102.4 MB)
__device__ float g_h2[(size_t)NN * HD];     // layer2 h = g1@W2           (25.6 MB)
__device__ float g_as1[NN * HEADS];
__device__ float g_ad1[NN * HEADS];
__device__ float g_as2[NN];
__device__ float g_ad2[NN];
__device__ int   g_deg[NN];
__device__ int   g_rowptr[NN + 1];
__device__ int   g_cursor[NN];
__device__ int   g_blksums[256];
__device__ int   g_srcs[ET];                // CSR-by-dst src indices (13.2 MB)

__device__ __forceinline__ float lrelu(float x) { return fmaxf(x, 0.2f * x); }
__device__ __forceinline__ float eluf(float x)  { return x > 0.f ? x : expm1f(x); }

__device__ __forceinline__ unsigned f2tf32(float f) {
    unsigned u;
    asm("cvt.rna.tf32.f32 %0, %1;" : "=r"(u) : "f"(f));
    return u;
}

__device__ __forceinline__ void mma_tf32(float* d, const unsigned* a, const unsigned* b) {
    asm volatile(
        "mma.sync.aligned.m16n8k8.row.col.f32.tf32.tf32.f32 "
        "{%0,%1,%2,%3}, {%4,%5,%6,%7}, {%8,%9}, {%0,%1,%2,%3};\n"
        : "+f"(d[0]), "+f"(d[1]), "+f"(d[2]), "+f"(d[3])
        : "r"(a[0]), "r"(a[1]), "r"(a[2]), "r"(a[3]), "r"(b[0]), "r"(b[1]));
}

// ---------------- tf32 tensor-core GEMM: BM=128, BN=64, BK=16 ----------------
template<int N, int K>
__device__ __forceinline__ void mma_gemm(const float* __restrict__ A,
                                         const float* __restrict__ Bg,
                                         float* __restrict__ C, int M) {
    constexpr int BM = 128, BN = 64, BK = 16;
    constexpr int ASTR = 20;   // BK+4 floats: bank(20r+c) covers 0..31
    constexpr int BSTR = 72;   // BN+8 floats: bank(8c+r) covers 0..31
    constexpr int NT = K / BK;
    __shared__ unsigned As[2][BM * ASTR];
    __shared__ unsigned Bs[2][BK * BSTR];

    const int tid  = threadIdx.x;
    const int lane = tid & 31, wid = tid >> 5;
    const int wm = wid & 3, wn = wid >> 2;
    const int r = lane >> 2, cq = lane & 3;
    const int row0 = blockIdx.y * BM;
    const int col0 = blockIdx.x * BN;

    const int ar0 = tid >> 2,          ak0 = (tid & 3) << 2;
    const int ar1 = (tid + 256) >> 2,  ak1 = (tid & 3) << 2;
    const int bkr = tid >> 4,          bnc = (tid & 15) << 2;

    float4 aR0, aR1, bR;

    float acc[2][4][4];
#pragma unroll
    for (int mt = 0; mt < 2; mt++)
#pragma unroll
        for (int nt = 0; nt < 4; nt++)
#pragma unroll
            for (int i = 0; i < 4; i++) acc[mt][nt][i] = 0.f;

    {
        aR0 = make_float4(0.f, 0.f, 0.f, 0.f);
        aR1 = make_float4(0.f, 0.f, 0.f, 0.f);
        if (row0 + ar0 < M) aR0 = *(const float4*)(A + (size_t)(row0 + ar0) * K + ak0);
        if (row0 + ar1 < M) aR1 = *(const float4*)(A + (size_t)(row0 + ar1) * K + ak1);
        bR = *(const float4*)(Bg + (size_t)bkr * N + col0 + bnc);
        *(uint4*)&As[0][ar0 * ASTR + ak0] =
            make_uint4(f2tf32(aR0.x), f2tf32(aR0.y), f2tf32(aR0.z), f2tf32(aR0.w));
        *(uint4*)&As[0][ar1 * ASTR + ak1] =
            make_uint4(f2tf32(aR1.x), f2tf32(aR1.y), f2tf32(aR1.z), f2tf32(aR1.w));
        *(uint4*)&Bs[0][bkr * BSTR + bnc] =
            make_uint4(f2tf32(bR.x), f2tf32(bR.y), f2tf32(bR.z), f2tf32(bR.w));
    }
    __syncthreads();

#pragma unroll 1
    for (int it = 0; it < NT; it++) {
        const int buf = it & 1;
        if (it + 1 < NT) {
            const int k0 = (it + 1) * BK;
            aR0 = make_float4(0.f, 0.f, 0.f, 0.f);
            aR1 = make_float4(0.f, 0.f, 0.f, 0.f);
            if (row0 + ar0 < M) aR0 = *(const float4*)(A + (size_t)(row0 + ar0) * K + k0 + ak0);
            if (row0 + ar1 < M) aR1 = *(const float4*)(A + (size_t)(row0 + ar1) * K + k0 + ak1);
            bR = *(const float4*)(Bg + (size_t)(k0 + bkr) * N + col0 + bnc);
        }

#pragma unroll
        for (int kt = 0; kt < 2; kt++) {
            unsigned a[2][4], b[4][2];
#pragma unroll
            for (int mt = 0; mt < 2; mt++) {
                const int mb = wm * 32 + mt * 16;
                const unsigned* ap = &As[buf][0];
                a[mt][0] = ap[(mb + r) * ASTR + kt * 8 + cq];
                a[mt][1] = ap[(mb + r + 8) * ASTR + kt * 8 + cq];
                a[mt][2] = ap[(mb + r) * ASTR + kt * 8 + cq + 4];
                a[mt][3] = ap[(mb + r + 8) * ASTR + kt * 8 + cq + 4];
            }
#pragma unroll
            for (int nt = 0; nt < 4; nt++) {
                const int nb = wn * 32 + nt * 8 + r;
                b[nt][0] = Bs[buf][(kt * 8 + cq) * BSTR + nb];
                b[nt][1] = Bs[buf][(kt * 8 + cq + 4) * BSTR + nb];
            }
#pragma unroll
            for (int mt = 0; mt < 2; mt++)
#pragma unroll
                for (int nt = 0; nt < 4; nt++)
                    mma_tf32(acc[mt][nt], a[mt], b[nt]);
        }

        if (it + 1 < NT) {
            const int nb = buf ^ 1;
            *(uint4*)&As[nb][ar0 * ASTR + ak0] =
                make_uint4(f2tf32(aR0.x), f2tf32(aR0.y), f2tf32(aR0.z), f2tf32(aR0.w));
            *(uint4*)&As[nb][ar1 * ASTR + ak1] =
                make_uint4(f2tf32(aR1.x), f2tf32(aR1.y), f2tf32(aR1.z), f2tf32(aR1.w));
            *(uint4*)&Bs[nb][bkr * BSTR + bnc] =
                make_uint4(f2tf32(bR.x), f2tf32(bR.y), f2tf32(bR.z), f2tf32(bR.w));
        }
        __syncthreads();
    }

#pragma unroll
    for (int mt = 0; mt < 2; mt++) {
        const int m_lo = row0 + wm * 32 + mt * 16 + r;
        const int m_hi = m_lo + 8;
#pragma unroll
        for (int nt = 0; nt < 4; nt++) {
            const int n = col0 + wn * 32 + nt * 8 + cq * 2;
            if (m_lo < M)
                *(float2*)(C + (size_t)m_lo * N + n) = make_float2(acc[mt][nt][0], acc[mt][nt][1]);
            if (m_hi < M)
                *(float2*)(C + (size_t)m_hi * N + n) = make_float2(acc[mt][nt][2], acc[mt][nt][3]);
        }
    }
}

__global__ void __launch_bounds__(256) k_gemm1(const float* __restrict__ A,
                                               const float* __restrict__ B) {
    mma_gemm<D1, INDIM>(A, B, g_h1, NN);
}
__global__ void __launch_bounds__(256) k_gemm2(const float* __restrict__ B) {
    mma_gemm<HD, D1>(g_g1, B, g_h2, NN);
}

// ---------------- attention coefficient dots ----------------
__global__ void k_alpha1(const float* __restrict__ a_src1, const float* __restrict__ a_dst1) {
    int t = blockIdx.x * blockDim.x + threadIdx.x;
    if (t >= NN * HEADS) return;
    int n = t >> 2, h = t & 3;
    const float4* hp = (const float4*)(g_h1 + (size_t)n * D1 + h * HD);
    const float4* sp = (const float4*)(a_src1 + h * HD);
    const float4* dp = (const float4*)(a_dst1 + h * HD);
    float ss = 0.f, dd = 0.f;
#pragma unroll
    for (int i = 0; i < HD / 4; i++) {
        float4 hv = hp[i], sv = sp[i], dv = dp[i];
        ss += hv.x * sv.x + hv.y * sv.y + hv.z * sv.z + hv.w * sv.w;
        dd += hv.x * dv.x + hv.y * dv.y + hv.z * dv.z + hv.w * dv.w;
    }
    g_as1[t] = ss;
    g_ad1[t] = dd;
}

__global__ void k_alpha2(const float* __restrict__ a_src2, const float* __restrict__ a_dst2) {
    int n = blockIdx.x * blockDim.x + threadIdx.x;
    if (n >= NN) return;
    const float4* hp = (const float4*)(g_h2 + (size_t)n * HD);
    const float4* sp = (const float4*)a_src2;
    const float4* dp = (const float4*)a_dst2;
    float ss = 0.f, dd = 0.f;
#pragma unroll
    for (int i = 0; i < HD / 4; i++) {
        float4 hv = hp[i], sv = sp[i], dv = dp[i];
        ss += hv.x * sv.x + hv.y * sv.y + hv.z * sv.z + hv.w * sv.w;
        dd += hv.x * dv.x + hv.y * dv.y + hv.z * dv.z + hv.w * dv.w;
    }
    g_as2[n] = ss;
    g_ad2[n] = dd;
}

// ---------------- CSR build (counting sort by dst) ----------------
__global__ void k_deg_init() {
    int i = blockIdx.x * blockDim.x + threadIdx.x;
    if (i < NN) g_deg[i] = 1;   // self-loop pre-counted
}
__global__ void k_hist(const int* __restrict__ dst) {
    int i = blockIdx.x * blockDim.x + threadIdx.x;
    if (i < EE) atomicAdd(&g_deg[dst[i]], 1);
}

#define SCAN_B 512
#define SCAN_NB ((NN + SCAN_B - 1) / SCAN_B)   // 196

__global__ void k_scan1() {
    __shared__ int sm[SCAN_B];
    int i = blockIdx.x * SCAN_B + threadIdx.x;
    int v = (i < NN) ? g_deg[i] : 0;
    sm[threadIdx.x] = v;
    __syncthreads();
    for (int off = 1; off < SCAN_B; off <<= 1) {
        int t = (threadIdx.x >= off) ? sm[threadIdx.x - off] : 0;
        __syncthreads();
        sm[threadIdx.x] += t;
        __syncthreads();
    }
    if (i < NN) g_rowptr[i] = sm[threadIdx.x] - v;   // exclusive within block
    if (threadIdx.x == SCAN_B - 1) g_blksums[blockIdx.x] = sm[threadIdx.x];
}
__global__ void k_scan2() {
    __shared__ int sm[256];
    int v = (threadIdx.x < SCAN_NB) ? g_blksums[threadIdx.x] : 0;
    sm[threadIdx.x] = v;
    __syncthreads();
    for (int off = 1; off < 256; off <<= 1) {
        int t = (threadIdx.x >= off) ? sm[threadIdx.x - off] : 0;
        __syncthreads();
        sm[threadIdx.x] += t;
        __syncthreads();
    }
    g_blksums[threadIdx.x] = sm[threadIdx.x] - v;    // exclusive
}
__global__ void k_scan3() {
    int i = blockIdx.x * blockDim.x + threadIdx.x;
    if (i < NN) {
        int r = g_rowptr[i] + g_blksums[i / SCAN_B];
        g_rowptr[i] = r;
        g_cursor[i] = r;
    } else if (i == NN) {
        g_rowptr[NN] = ET;
    }
}
__global__ void k_scatter(const int* __restrict__ ei) {
    int i = blockIdx.x * blockDim.x + threadIdx.x;
    if (i >= ET) return;
    int s, d;
    if (i < EE) { s = ei[i]; d = ei[EE + i]; }
    else        { s = d = i - EE; }
    int pos = atomicAdd(&g_cursor[d], 1);
    g_srcs[pos] = s;
}

// ---------------- layer-1 aggregation: one warp per dst node ----------------
// Single online-softmax stats pass, then weighted aggregation pass.
__global__ void k_agg1(const float* __restrict__ b1) {
    int gw = (blockIdx.x * blockDim.x + threadIdx.x) >> 5;
    if (gw >= NN) return;
    const int lane = threadIdx.x & 31;
    const int v = gw;
    const int r0 = g_rowptr[v], r1 = g_rowptr[v + 1];
    const float4 adv = ((const float4*)g_ad1)[v];

    // pass 1 (online): per-head running (max, sum) per lane
    float mx0 = -1e30f, mx1 = -1e30f, mx2 = -1e30f, mx3 = -1e30f;
    float s0 = 0.f, s1 = 0.f, s2 = 0.f, s3 = 0.f;
    for (int e = r0 + lane; e < r1; e += 32) {
        int s = g_srcs[e];
        float4 as = ((const float4*)g_as1)[s];
        float w0 = lrelu(as.x + adv.x);
        float w1 = lrelu(as.y + adv.y);
        float w2 = lrelu(as.z + adv.z);
        float w3 = lrelu(as.w + adv.w);
        float n0 = fmaxf(mx0, w0), n1 = fmaxf(mx1, w1);
        float n2 = fmaxf(mx2, w2), n3 = fmaxf(mx3, w3);
        s0 = s0 * __expf(mx0 - n0) + __expf(w0 - n0);
        s1 = s1 * __expf(mx1 - n1) + __expf(w1 - n1);
        s2 = s2 * __expf(mx2 - n2) + __expf(w2 - n2);
        s3 = s3 * __expf(mx3 - n3) + __expf(w3 - n3);
        mx0 = n0; mx1 = n1; mx2 = n2; mx3 = n3;
    }
#pragma unroll
    for (int o = 16; o; o >>= 1) {
        float om, os, nm;
        om = __shfl_xor_sync(0xffffffffu, mx0, o); os = __shfl_xor_sync(0xffffffffu, s0, o);
        nm = fmaxf(mx0, om); s0 = s0 * __expf(mx0 - nm) + os * __expf(om - nm); mx0 = nm;
        om = __shfl_xor_sync(0xffffffffu, mx1, o); os = __shfl_xor_sync(0xffffffffu, s1, o);
        nm = fmaxf(mx1, om); s1 = s1 * __expf(mx1 - nm) + os * __expf(om - nm); mx1 = nm;
        om = __shfl_xor_sync(0xffffffffu, mx2, o); os = __shfl_xor_sync(0xffffffffu, s2, o);
        nm = fmaxf(mx2, om); s2 = s2 * __expf(mx2 - nm) + os * __expf(om - nm); mx2 = nm;
        om = __shfl_xor_sync(0xffffffffu, mx3, o); os = __shfl_xor_sync(0xffffffffu, s3, o);
        nm = fmaxf(mx3, om); s3 = s3 * __expf(mx3 - nm) + os * __expf(om - nm); mx3 = nm;
    }
    const float i0 = 1.f / s0, i1 = 1.f / s1, i2 = 1.f / s2, i3 = 1.f / s3;

    // pass 2: weighted aggregation. lane owns elems [4*lane,4*lane+4) (heads 0/1)
    // and [128+4*lane, ...) (heads 2/3).
    const int hA = lane >> 4;                       // 0 or 1
    const float adA = hA ? adv.y : adv.x;
    const float adB = hA ? adv.w : adv.z;
    const float mA  = hA ? mx1 : mx0;
    const float mB  = hA ? mx3 : mx2;
    const float iA  = hA ? i1 : i0;
    const float iB  = hA ? i3 : i2;

    float4 acc0 = make_float4(0.f, 0.f, 0.f, 0.f);
    float4 acc1 = make_float4(0.f, 0.f, 0.f, 0.f);
    int s = (r0 < r1) ? g_srcs[r0] : 0;
    for (int e = r0; e < r1; e++) {
        int snext = (e + 1 < r1) ? g_srcs[e + 1] : 0;
        float aA = __expf(lrelu(g_as1[s * 4 + hA]     + adA) - mA) * iA;
        float aB = __expf(lrelu(g_as1[s * 4 + 2 + hA] + adB) - mB) * iB;
        const float4* hp = (const float4*)(g_h1 + (size_t)s * D1);
        float4 x0 = hp[lane];
        float4 x1 = hp[lane + 32];
        acc0.x = fmaf(x0.x, aA, acc0.x);
        acc0.y = fmaf(x0.y, aA, acc0.y);
        acc0.z = fmaf(x0.z, aA, acc0.z);
        acc0.w = fmaf(x0.w, aA, acc0.w);
        acc1.x = fmaf(x1.x, aB, acc1.x);
        acc1.y = fmaf(x1.y, aB, acc1.y);
        acc1.z = fmaf(x1.z, aB, acc1.z);
        acc1.w = fmaf(x1.w, aB, acc1.w);
        s = snext;
    }

    // epilogue: +b1, ELU, streaming store (don't evict h1 from L2)
    float4 bb0 = ((const float4*)b1)[lane];
    float4 bb1 = ((const float4*)b1)[lane + 32];
    float4 o0, o1;
    o0.x = eluf(acc0.x + bb0.x); o0.y = eluf(acc0.y + bb0.y);
    o0.z = eluf(acc0.z + bb0.z); o0.w = eluf(acc0.w + bb0.w);
    o1.x = eluf(acc1.x + bb1.x); o1.y = eluf(acc1.y + bb1.y);
    o1.z = eluf(acc1.z + bb1.z); o1.w = eluf(acc1.w + bb1.w);
    float4* op = (float4*)(g_g1 + (size_t)v * D1);
    __stcs(op + lane, o0);
    __stcs(op + lane + 32, o1);
}

// ---------------- layer-2 aggregation + ELU + final linear ----------------
__global__ void k_agg2(const float* __restrict__ b2, const float* __restrict__ lw,
                       const float* __restrict__ lb, float* __restrict__ out) {
    int gw = (blockIdx.x * blockDim.x + threadIdx.x) >> 5;
    if (gw >= NN) return;
    const int lane = threadIdx.x & 31;
    const int v = gw;
    const int r0 = g_rowptr[v], r1 = g_rowptr[v + 1];
    const float adv = g_ad2[v];

    float mx = -1e30f, sm = 0.f;
    for (int e = r0 + lane; e < r1; e += 32) {
        float w = lrelu(g_as2[g_srcs[e]] + adv);
        float nm = fmaxf(mx, w);
        sm = sm * __expf(mx - nm) + __expf(w - nm);
        mx = nm;
    }
#pragma unroll
    for (int o = 16; o; o >>= 1) {
        float om = __shfl_xor_sync(0xffffffffu, mx, o);
        float os = __shfl_xor_sync(0xffffffffu, sm, o);
        float nm = fmaxf(mx, om);
        sm = sm * __expf(mx - nm) + os * __expf(om - nm);
        mx = nm;
    }
    const float inv = 1.f / sm;

    float2 acc = make_float2(0.f, 0.f);
    int s = (r0 < r1) ? g_srcs[r0] : 0;
    for (int e = r0; e < r1; e++) {
        int snext = (e + 1 < r1) ? g_srcs[e + 1] : 0;
        float a = __expf(lrelu(g_as2[s] + adv) - mx) * inv;
        float2 x = ((const float2*)(g_h2 + (size_t)s * HD))[lane];
        acc.x = fmaf(x.x, a, acc.x);
        acc.y = fmaf(x.y, a, acc.y);
        s = snext;
    }

    const int d = 2 * lane;
    float t0 = eluf(acc.x + b2[d]);
    float t1 = eluf(acc.y + b2[d + 1]);
    float y0 = t0 * lw[d * 2]     + t1 * lw[d * 2 + 2];
    float y1 = t0 * lw[d * 2 + 1] + t1 * lw[d * 2 + 3];
#pragma unroll
    for (int o = 16; o; o >>= 1) {
        y0 += __shfl_xor_sync(0xffffffffu, y0, o);
        y1 += __shfl_xor_sync(0xffffffffu, y1, o);
    }
    if (lane == 0) {
        out[2 * v]     = y0 + lb[0];
        out[2 * v + 1] = y1 + lb[1];
    }
}

// ---------------- launch ----------------
extern "C" void kernel_launch(void* const* d_in, const int* in_sizes, int n_in,
                              void* d_out, int out_size) {
    const float* x      = (const float*)d_in[0];
    const int*   ei     = (const int*)d_in[1];     // int32: jax default x64 disabled
    const float* W1     = (const float*)d_in[2];
    const float* a_src1 = (const float*)d_in[3];
    const float* a_dst1 = (const float*)d_in[4];
    const float* b1     = (const float*)d_in[5];
    const float* W2     = (const float*)d_in[6];
    const float* a_src2 = (const float*)d_in[7];
    const float* a_dst2 = (const float*)d_in[8];
    const float* b2     = (const float*)d_in[9];
    const float* lw     = (const float*)d_in[10];
    const float* lb     = (const float*)d_in[11];
    float*       out    = (float*)d_out;

    // Lazily created once on the (uncaptured) correctness call; reused by capture.
    static cudaStream_t s1 = nullptr;
    static cudaEvent_t evRoot = nullptr, evCsr = nullptr;
    if (s1 == nullptr) {
        cudaStreamCreateWithFlags(&s1, cudaStreamNonBlocking);
        cudaEventCreateWithFlags(&evRoot, cudaEventDisableTiming);
        cudaEventCreateWithFlags(&evCsr, cudaEventDisableTiming);
    }

    // fork: CSR chain on s1, GEMM1 chain on the main stream
    cudaEventRecord(evRoot, 0);
    cudaStreamWaitEvent(s1, evRoot, 0);

    k_deg_init<<<(NN + 255) / 256, 256, 0, s1>>>();
    k_hist<<<(EE + 255) / 256, 256, 0, s1>>>(ei + EE);
    k_scan1<<<SCAN_NB, SCAN_B, 0, s1>>>();

    k_gemm1<<<dim3(D1 / 64, (NN + 127) / 128), 256>>>(x, W1);   // profiled slot

    k_scan2<<<1, 256, 0, s1>>>();
    k_scan3<<<(NN + 1 + 255) / 256, 256, 0, s1>>>();
    k_scatter<<<(ET + 255) / 256, 256, 0, s1>>>(ei);
    cudaEventRecord(evCsr, s1);

    k_alpha1<<<(NN * HEADS + 255) / 256, 256>>>(a_src1, a_dst1);

    // join: agg1 needs both CSR and alpha1
    cudaStreamWaitEvent(0, evCsr, 0);
    k_agg1<<<(NN + 7) / 8, 256>>>(b1);

    // layer 2
    k_gemm2<<<dim3(1, (NN + 127) / 128), 256>>>(W2);
    k_alpha2<<<(NN + 255) / 256, 256>>>(a_src2, a_dst2);
    k_agg2<<<(NN + 7) / 8, 256>>>(b2, lw, lb, out);
}

// round 5
// speedup vs baseline: 1.5844x; 1.2990x over previous
#include <cuda_runtime.h>
#include <cuda_fp16.h>
#include <cstdint>

#define NN 100000
#define EE 3200000
#define ET (EE + NN)           // 3,300,000 edges incl. self loops
#define HEADS 4
#define HD 64
#define D1 256                 // HEADS*HD
#define INDIM 128

// ---------------- scratch (static device globals; no allocs) ----------------
__device__ __half g_h1h[(size_t)NN * D1];   // layer1 h (fp16)            (51.2 MB)
__device__ __half g_g1h[(size_t)NN * D1];   // elu(agg1+b1) (fp16)        (51.2 MB)
__device__ __half g_h2h[(size_t)NN * HD];   // layer2 h (fp16)            (12.8 MB)
__device__ float g_as1[NN * HEADS];
__device__ float g_ad1[NN * HEADS];
__device__ float g_as2[NN];
__device__ float g_ad2[NN];
__device__ int   g_deg[NN];
__device__ int   g_rowptr[NN + 1];
__device__ int   g_cursor[NN];
__device__ int   g_blksums[256];
__device__ int   g_srcs[ET];                // CSR-by-dst src indices (13.2 MB)

__device__ __forceinline__ float lrelu(float x) { return fmaxf(x, 0.2f * x); }
__device__ __forceinline__ float eluf(float x)  { return x > 0.f ? x : expm1f(x); }

__device__ __forceinline__ unsigned f2tf32(float f) {
    unsigned u;
    asm("cvt.rna.tf32.f32 %0, %1;" : "=r"(u) : "f"(f));
    return u;
}

__device__ __forceinline__ void mma_tf32(float* d, const unsigned* a, const unsigned* b) {
    asm volatile(
        "mma.sync.aligned.m16n8k8.row.col.f32.tf32.tf32.f32 "
        "{%0,%1,%2,%3}, {%4,%5,%6,%7}, {%8,%9}, {%0,%1,%2,%3};\n"
        : "+f"(d[0]), "+f"(d[1]), "+f"(d[2]), "+f"(d[3])
        : "r"(a[0]), "r"(a[1]), "r"(a[2]), "r"(a[3]), "r"(b[0]), "r"(b[1]));
}

// ---------------- tf32 tensor-core GEMM cores ----------------
// BM=128, BN=64, BK=16; 8 warps (4m x 2n); warp does 2x4 m16n8k8 tiles.
// AHALF: A operand is fp16 in gmem (converted to tf32 at smem store).
template<int N, int K, bool AHALF>
__device__ __forceinline__ void mma_gemm(const void* __restrict__ Av,
                                         const float* __restrict__ Bg,
                                         __half* __restrict__ C, int M) {
    constexpr int BM = 128, BN = 64, BK = 16;
    constexpr int ASTR = 20;   // BK+4: bank(20r+c) covers 0..31
    constexpr int BSTR = 72;   // BN+8: bank(8c+r) covers 0..31
    constexpr int NT = K / BK;
    __shared__ unsigned As[2][BM * ASTR];
    __shared__ unsigned Bs[2][BK * BSTR];

    const int tid  = threadIdx.x;
    const int lane = tid & 31, wid = tid >> 5;
    const int wm = wid & 3, wn = wid >> 2;
    const int r = lane >> 2, cq = lane & 3;
    const int row0 = blockIdx.y * BM;
    const int col0 = blockIdx.x * BN;

    // fp32 A staging: 128x16 fl = 512 float4 (2/thread)
    const int ar0 = tid >> 2,          ak0 = (tid & 3) << 2;
    const int ar1 = (tid + 256) >> 2;
    // fp16 A staging: 128x16 halves = 256 uint4 (1/thread, 8 halves)
    const int ahr = tid >> 1,          ahk = (tid & 1) << 3;
    // B staging: 16x64 fl = 256 float4
    const int bkr = tid >> 4,          bnc = (tid & 15) << 2;

    const float*  Af = (const float*)Av;
    const __half* Ah = (const __half*)Av;

    float4 aR0, aR1, bR;
    uint4 aH;

    float acc[2][4][4];
#pragma unroll
    for (int mt = 0; mt < 2; mt++)
#pragma unroll
        for (int nt = 0; nt < 4; nt++)
#pragma unroll
            for (int i = 0; i < 4; i++) acc[mt][nt][i] = 0.f;

    auto stageA = [&](int buf, int k0) {
        if (AHALF) {
            aH = make_uint4(0, 0, 0, 0);
            if (row0 + ahr < M)
                aH = *(const uint4*)(Ah + (size_t)(row0 + ahr) * K + k0 + ahk);
            const __half2* hp = (const __half2*)&aH;
#pragma unroll
            for (int i = 0; i < 4; i++) {
                float2 f = __half22float2(hp[i]);
                As[buf][ahr * ASTR + ahk + 2 * i]     = f2tf32(f.x);
                As[buf][ahr * ASTR + ahk + 2 * i + 1] = f2tf32(f.y);
            }
        } else {
            aR0 = make_float4(0.f, 0.f, 0.f, 0.f);
            aR1 = make_float4(0.f, 0.f, 0.f, 0.f);
            if (row0 + ar0 < M) aR0 = *(const float4*)(Af + (size_t)(row0 + ar0) * K + k0 + ak0);
            if (row0 + ar1 < M) aR1 = *(const float4*)(Af + (size_t)(row0 + ar1) * K + k0 + ak0);
            *(uint4*)&As[buf][ar0 * ASTR + ak0] =
                make_uint4(f2tf32(aR0.x), f2tf32(aR0.y), f2tf32(aR0.z), f2tf32(aR0.w));
            *(uint4*)&As[buf][ar1 * ASTR + ak0] =
                make_uint4(f2tf32(aR1.x), f2tf32(aR1.y), f2tf32(aR1.z), f2tf32(aR1.w));
        }
    };
    auto stageB = [&](int buf, int k0) {
        bR = *(const float4*)(Bg + (size_t)(k0 + bkr) * N + col0 + bnc);
        *(uint4*)&Bs[buf][bkr * BSTR + bnc] =
            make_uint4(f2tf32(bR.x), f2tf32(bR.y), f2tf32(bR.z), f2tf32(bR.w));
    };

    stageA(0, 0);
    stageB(0, 0);
    __syncthreads();

#pragma unroll 1
    for (int it = 0; it < NT; it++) {
        const int buf = it & 1;

#pragma unroll
        for (int kt = 0; kt < 2; kt++) {
            unsigned a[2][4], b[4][2];
#pragma unroll
            for (int mt = 0; mt < 2; mt++) {
                const int mb = wm * 32 + mt * 16;
                const unsigned* ap = &As[buf][0];
                a[mt][0] = ap[(mb + r) * ASTR + kt * 8 + cq];
                a[mt][1] = ap[(mb + r + 8) * ASTR + kt * 8 + cq];
                a[mt][2] = ap[(mb + r) * ASTR + kt * 8 + cq + 4];
                a[mt][3] = ap[(mb + r + 8) * ASTR + kt * 8 + cq + 4];
            }
#pragma unroll
            for (int nt = 0; nt < 4; nt++) {
                const int nb = wn * 32 + nt * 8 + r;
                b[nt][0] = Bs[buf][(kt * 8 + cq) * BSTR + nb];
                b[nt][1] = Bs[buf][(kt * 8 + cq + 4) * BSTR + nb];
            }
#pragma unroll
            for (int mt = 0; mt < 2; mt++)
#pragma unroll
                for (int nt = 0; nt < 4; nt++)
                    mma_tf32(acc[mt][nt], a[mt], b[nt]);
        }

        if (it + 1 < NT) {
            stageA(buf ^ 1, (it + 1) * BK);
            stageB(buf ^ 1, (it + 1) * BK);
        }
        __syncthreads();
    }

    // epilogue: store fp16
#pragma unroll
    for (int mt = 0; mt < 2; mt++) {
        const int m_lo = row0 + wm * 32 + mt * 16 + r;
        const int m_hi = m_lo + 8;
#pragma unroll
        for (int nt = 0; nt < 4; nt++) {
            const int n = col0 + wn * 32 + nt * 8 + cq * 2;
            if (m_lo < M)
                *(__half2*)(C + (size_t)m_lo * N + n) =
                    __floats2half2_rn(acc[mt][nt][0], acc[mt][nt][1]);
            if (m_hi < M)
                *(__half2*)(C + (size_t)m_hi * N + n) =
                    __floats2half2_rn(acc[mt][nt][2], acc[mt][nt][3]);
        }
    }
}

__global__ void __launch_bounds__(256) k_gemm1(const float* __restrict__ A,
                                               const float* __restrict__ B) {
    mma_gemm<D1, INDIM, false>(A, B, g_h1h, NN);
}
__global__ void __launch_bounds__(256) k_gemm2(const float* __restrict__ B) {
    mma_gemm<HD, D1, true>(g_g1h, B, g_h2h, NN);
}

// ---------------- attention coefficient dots (read fp16 h) ----------------
__global__ void k_alpha1(const float* __restrict__ a_src1, const float* __restrict__ a_dst1) {
    int t = blockIdx.x * blockDim.x + threadIdx.x;
    if (t >= NN * HEADS) return;
    int n = t >> 2, h = t & 3;
    const uint4* hp = (const uint4*)(g_h1h + (size_t)n * D1 + h * HD);
    const float* sp = a_src1 + h * HD;
    const float* dp = a_dst1 + h * HD;
    float ss = 0.f, dd = 0.f;
#pragma unroll
    for (int i = 0; i < HD / 8; i++) {
        uint4 hv = hp[i];
        const __half2* h2 = (const __half2*)&hv;
#pragma unroll
        for (int j = 0; j < 4; j++) {
            float2 f = __half22float2(h2[j]);
            ss += f.x * sp[i * 8 + 2 * j] + f.y * sp[i * 8 + 2 * j + 1];
            dd += f.x * dp[i * 8 + 2 * j] + f.y * dp[i * 8 + 2 * j + 1];
        }
    }
    g_as1[t] = ss;
    g_ad1[t] = dd;
}

__global__ void k_alpha2(const float* __restrict__ a_src2, const float* __restrict__ a_dst2) {
    int n = blockIdx.x * blockDim.x + threadIdx.x;
    if (n >= NN) return;
    const uint4* hp = (const uint4*)(g_h2h + (size_t)n * HD);
    float ss = 0.f, dd = 0.f;
#pragma unroll
    for (int i = 0; i < HD / 8; i++) {
        uint4 hv = hp[i];
        const __half2* h2 = (const __half2*)&hv;
#pragma unroll
        for (int j = 0; j < 4; j++) {
            float2 f = __half22float2(h2[j]);
            ss += f.x * a_src2[i * 8 + 2 * j] + f.y * a_src2[i * 8 + 2 * j + 1];
            dd += f.x * a_dst2[i * 8 + 2 * j] + f.y * a_dst2[i * 8 + 2 * j + 1];
        }
    }
    g_as2[n] = ss;
    g_ad2[n] = dd;
}

// ---------------- CSR build (counting sort by dst) ----------------
__global__ void k_deg_init() {
    int i = blockIdx.x * blockDim.x + threadIdx.x;
    if (i < NN) g_deg[i] = 1;   // self-loop pre-counted
}
__global__ void k_hist(const int* __restrict__ dst) {
    int i = blockIdx.x * blockDim.x + threadIdx.x;
    if (i < EE) atomicAdd(&g_deg[dst[i]], 1);
}

#define SCAN_B 512
#define SCAN_NB ((NN + SCAN_B - 1) / SCAN_B)   // 196

__global__ void k_scan1() {
    __shared__ int sm[SCAN_B];
    int i = blockIdx.x * SCAN_B + threadIdx.x;
    int v = (i < NN) ? g_deg[i] : 0;
    sm[threadIdx.x] = v;
    __syncthreads();
    for (int off = 1; off < SCAN_B; off <<= 1) {
        int t = (threadIdx.x >= off) ? sm[threadIdx.x - off] : 0;
        __syncthreads();
        sm[threadIdx.x] += t;
        __syncthreads();
    }
    if (i < NN) g_rowptr[i] = sm[threadIdx.x] - v;
    if (threadIdx.x == SCAN_B - 1) g_blksums[blockIdx.x] = sm[threadIdx.x];
}
__global__ void k_scan2() {
    __shared__ int sm[256];
    int v = (threadIdx.x < SCAN_NB) ? g_blksums[threadIdx.x] : 0;
    sm[threadIdx.x] = v;
    __syncthreads();
    for (int off = 1; off < 256; off <<= 1) {
        int t = (threadIdx.x >= off) ? sm[threadIdx.x - off] : 0;
        __syncthreads();
        sm[threadIdx.x] += t;
        __syncthreads();
    }
    g_blksums[threadIdx.x] = sm[threadIdx.x] - v;
}
__global__ void k_scan3() {
    int i = blockIdx.x * blockDim.x + threadIdx.x;
    if (i < NN) {
        int r = g_rowptr[i] + g_blksums[i / SCAN_B];
        g_rowptr[i] = r;
        g_cursor[i] = r;
    } else if (i == NN) {
        g_rowptr[NN] = ET;
    }
}
__global__ void k_scatter(const int* __restrict__ ei) {
    int i = blockIdx.x * blockDim.x + threadIdx.x;
    if (i >= ET) return;
    int s, d;
    if (i < EE) { s = ei[i]; d = ei[EE + i]; }
    else        { s = d = i - EE; }
    int pos = atomicAdd(&g_cursor[d], 1);
    g_srcs[pos] = s;
}

// ---------------- layer-1 aggregation: one warp per dst node ----------------
__global__ void k_agg1(const float* __restrict__ b1) {
    int gw = (blockIdx.x * blockDim.x + threadIdx.x) >> 5;
    if (gw >= NN) return;
    const int lane = threadIdx.x & 31;
    const int v = gw;
    const int r0 = g_rowptr[v], r1 = g_rowptr[v + 1];
    const float4 adv = ((const float4*)g_ad1)[v];

    // pass 1 (online softmax stats, lane-parallel over edges)
    float mx0 = -1e30f, mx1 = -1e30f, mx2 = -1e30f, mx3 = -1e30f;
    float s0 = 0.f, s1 = 0.f, s2 = 0.f, s3 = 0.f;
    for (int e = r0 + lane; e < r1; e += 32) {
        int s = g_srcs[e];
        float4 as = ((const float4*)g_as1)[s];
        float w0 = lrelu(as.x + adv.x);
        float w1 = lrelu(as.y + adv.y);
        float w2 = lrelu(as.z + adv.z);
        float w3 = lrelu(as.w + adv.w);
        float n0 = fmaxf(mx0, w0), n1 = fmaxf(mx1, w1);
        float n2 = fmaxf(mx2, w2), n3 = fmaxf(mx3, w3);
        s0 = s0 * __expf(mx0 - n0) + __expf(w0 - n0);
        s1 = s1 * __expf(mx1 - n1) + __expf(w1 - n1);
        s2 = s2 * __expf(mx2 - n2) + __expf(w2 - n2);
        s3 = s3 * __expf(mx3 - n3) + __expf(w3 - n3);
        mx0 = n0; mx1 = n1; mx2 = n2; mx3 = n3;
    }
#pragma unroll
    for (int o = 16; o; o >>= 1) {
        float om, os, nm;
        om = __shfl_xor_sync(0xffffffffu, mx0, o); os = __shfl_xor_sync(0xffffffffu, s0, o);
        nm = fmaxf(mx0, om); s0 = s0 * __expf(mx0 - nm) + os * __expf(om - nm); mx0 = nm;
        om = __shfl_xor_sync(0xffffffffu, mx1, o); os = __shfl_xor_sync(0xffffffffu, s1, o);
        nm = fmaxf(mx1, om); s1 = s1 * __expf(mx1 - nm) + os * __expf(om - nm); mx1 = nm;
        om = __shfl_xor_sync(0xffffffffu, mx2, o); os = __shfl_xor_sync(0xffffffffu, s2, o);
        nm = fmaxf(mx2, om); s2 = s2 * __expf(mx2 - nm) + os * __expf(om - nm); mx2 = nm;
        om = __shfl_xor_sync(0xffffffffu, mx3, o); os = __shfl_xor_sync(0xffffffffu, s3, o);
        nm = fmaxf(mx3, om); s3 = s3 * __expf(mx3 - nm) + os * __expf(om - nm); mx3 = nm;
    }

    // pass 2: weighted aggregation. lane owns 8 contiguous elems = one head slice.
    const int head = lane >> 3;                    // 8 lanes per head
    const float adh = head == 0 ? adv.x : head == 1 ? adv.y : head == 2 ? adv.z : adv.w;
    const float mh  = head == 0 ? mx0  : head == 1 ? mx1  : head == 2 ? mx2  : mx3;
    const float sh  = head == 0 ? s0   : head == 1 ? s1   : head == 2 ? s2   : s3;
    const float ih  = 1.f / sh;
    const float* asb = g_as1 + head;               // + s*4 per edge

    float acc[8];
#pragma unroll
    for (int i = 0; i < 8; i++) acc[i] = 0.f;

    const __half* h1b = g_h1h + lane * 8;
    int s = g_srcs[r0];
    for (int e = r0; e < r1; e++) {
        int snext = (e + 1 < r1) ? g_srcs[e + 1] : 0;
        float a = __expf(lrelu(asb[s * 4] + adh) - mh) * ih;
        uint4 hv = *(const uint4*)(h1b + (size_t)s * D1);
        const __half2* h2 = (const __half2*)&hv;
#pragma unroll
        for (int j = 0; j < 4; j++) {
            float2 f = __half22float2(h2[j]);
            acc[2 * j]     = fmaf(f.x, a, acc[2 * j]);
            acc[2 * j + 1] = fmaf(f.y, a, acc[2 * j + 1]);
        }
        s = snext;
    }

    // epilogue: +b1, ELU, store fp16 (single 16B store)
    const float* bb = b1 + lane * 8;
    __half2 oh[4];
#pragma unroll
    for (int j = 0; j < 4; j++)
        oh[j] = __floats2half2_rn(eluf(acc[2 * j] + bb[2 * j]),
                                  eluf(acc[2 * j + 1] + bb[2 * j + 1]));
    *(uint4*)(g_g1h + (size_t)v * D1 + lane * 8) = *(uint4*)oh;
}

// ---------------- layer-2 aggregation + ELU + final linear ----------------
__global__ void k_agg2(const float* __restrict__ b2, const float* __restrict__ lw,
                       const float* __restrict__ lb, float* __restrict__ out) {
    int gw = (blockIdx.x * blockDim.x + threadIdx.x) >> 5;
    if (gw >= NN) return;
    const int lane = threadIdx.x & 31;
    const int v = gw;
    const int r0 = g_rowptr[v], r1 = g_rowptr[v + 1];
    const float adv = g_ad2[v];

    float mx = -1e30f, sm = 0.f;
    for (int e = r0 + lane; e < r1; e += 32) {
        float w = lrelu(g_as2[g_srcs[e]] + adv);
        float nm = fmaxf(mx, w);
        sm = sm * __expf(mx - nm) + __expf(w - nm);
        mx = nm;
    }
#pragma unroll
    for (int o = 16; o; o >>= 1) {
        float om = __shfl_xor_sync(0xffffffffu, mx, o);
        float os = __shfl_xor_sync(0xffffffffu, sm, o);
        float nm = fmaxf(mx, om);
        sm = sm * __expf(mx - nm) + os * __expf(om - nm);
        mx = nm;
    }
    const float inv = 1.f / sm;

    float2 acc = make_float2(0.f, 0.f);
    const __half* h2b = g_h2h + lane * 2;
    int s = g_srcs[r0];
    for (int e = r0; e < r1; e++) {
        int snext = (e + 1 < r1) ? g_srcs[e + 1] : 0;
        float a = __expf(lrelu(g_as2[s] + adv) - mx) * inv;
        float2 x = __half22float2(*(const __half2*)(h2b + (size_t)s * HD));
        acc.x = fmaf(x.x, a, acc.x);
        acc.y = fmaf(x.y, a, acc.y);
        s = snext;
    }

    const int d = 2 * lane;
    float t0 = eluf(acc.x + b2[d]);
    float t1 = eluf(acc.y + b2[d + 1]);
    float y0 = t0 * lw[d * 2]     + t1 * lw[d * 2 + 2];
    float y1 = t0 * lw[d * 2 + 1] + t1 * lw[d * 2 + 3];
#pragma unroll
    for (int o = 16; o; o >>= 1) {
        y0 += __shfl_xor_sync(0xffffffffu, y0, o);
        y1 += __shfl_xor_sync(0xffffffffu, y1, o);
    }
    if (lane == 0) {
        out[2 * v]     = y0 + lb[0];
        out[2 * v + 1] = y1 + lb[1];
    }
}

// ---------------- launch ----------------
extern "C" void kernel_launch(void* const* d_in, const int* in_sizes, int n_in,
                              void* d_out, int out_size) {
    const float* x      = (const float*)d_in[0];
    const int*   ei     = (const int*)d_in[1];     // int32: jax default x64 disabled
    const float* W1     = (const float*)d_in[2];
    const float* a_src1 = (const float*)d_in[3];
    const float* a_dst1 = (const float*)d_in[4];
    const float* b1     = (const float*)d_in[5];
    const float* W2     = (const float*)d_in[6];
    const float* a_src2 = (const float*)d_in[7];
    const float* a_dst2 = (const float*)d_in[8];
    const float* b2     = (const float*)d_in[9];
    const float* lw     = (const float*)d_in[10];
    const float* lb     = (const float*)d_in[11];
    float*       out    = (float*)d_out;

    static cudaStream_t s1 = nullptr;
    static cudaEvent_t evRoot = nullptr, evCsr = nullptr;
    if (s1 == nullptr) {
        cudaStreamCreateWithFlags(&s1, cudaStreamNonBlocking);
        cudaEventCreateWithFlags(&evRoot, cudaEventDisableTiming);
        cudaEventCreateWithFlags(&evCsr, cudaEventDisableTiming);
    }

    // fork: CSR chain on s1, GEMM1 chain on the main stream
    cudaEventRecord(evRoot, 0);
    cudaStreamWaitEvent(s1, evRoot, 0);

    k_deg_init<<<(NN + 255) / 256, 256, 0, s1>>>();
    k_hist<<<(EE + 255) / 256, 256, 0, s1>>>(ei + EE);
    k_scan1<<<SCAN_NB, SCAN_B, 0, s1>>>();

    k_gemm1<<<dim3(D1 / 64, (NN + 127) / 128), 256>>>(x, W1);

    k_scan2<<<1, 256, 0, s1>>>();
    k_scan3<<<(NN + 1 + 255) / 256, 256, 0, s1>>>();
    k_scatter<<<(ET + 255) / 256, 256, 0, s1>>>(ei);
    cudaEventRecord(evCsr, s1);

    k_alpha1<<<(NN * HEADS + 255) / 256, 256>>>(a_src1, a_dst1);

    cudaStreamWaitEvent(0, evCsr, 0);
    k_agg1<<<(NN + 7) / 8, 256>>>(b1);

    // layer 2
    k_gemm2<<<dim3(1, (NN + 127) / 128), 256>>>(W2);
    k_alpha2<<<(NN + 255) / 256, 256>>>(a_src2, a_dst2);
    k_agg2<<<(NN + 7) / 8, 256>>>(b2, lw, lb, out);
}

// round 6
// speedup vs baseline: 1.6260x; 1.0262x over previous
#include <cuda_runtime.h>
#include <cuda_fp16.h>
#include <cstdint>

#define NN 100000
#define EE 3200000
#define ET (EE + NN)           // 3,300,000 edges incl. self loops
#define HEADS 4
#define HD 64
#define D1 256                 // HEADS*HD
#define INDIM 128

// ---------------- scratch (static device globals; no allocs) ----------------
__device__ __half g_h1h[(size_t)NN * D1];   // layer1 h (fp16)            (51.2 MB)
__device__ __half g_g1h[(size_t)NN * D1];   // elu(agg1+b1) (fp16)        (51.2 MB)
__device__ __half g_h2h[(size_t)NN * HD];   // layer2 h (fp16)            (12.8 MB)
__device__ float g_as1[NN * HEADS];
__device__ float g_ad1[NN * HEADS];
__device__ float g_as2[NN];
__device__ float g_ad2[NN];
__device__ int   g_deg[NN];
__device__ int   g_rowptr[NN + 1];
__device__ int   g_cursor[NN];
__device__ int   g_blksums[256];
__device__ int   g_srcs[ET];                // CSR-by-dst src indices (13.2 MB)

__device__ __forceinline__ float lrelu(float x) { return fmaxf(x, 0.2f * x); }
__device__ __forceinline__ float eluf(float x)  { return x > 0.f ? x : expm1f(x); }

__device__ __forceinline__ void mma_f16(float* d, const unsigned* a, const unsigned* b) {
    asm volatile(
        "mma.sync.aligned.m16n8k16.row.col.f32.f16.f16.f32 "
        "{%0,%1,%2,%3}, {%4,%5,%6,%7}, {%8,%9}, {%0,%1,%2,%3};\n"
        : "+f"(d[0]), "+f"(d[1]), "+f"(d[2]), "+f"(d[3])
        : "r"(a[0]), "r"(a[1]), "r"(a[2]), "r"(a[3]), "r"(b[0]), "r"(b[1]));
}

// ---------------- fp16 tensor-core GEMM: BM=128, BN=64, BK=16 ----------------
// 8 warps (4m x 2n); warp = 2x4 m16n8k16 tiles. A smem [m][k] stride 24 halves,
// B smem transposed [n][k] stride 24 halves -> all fragment loads are half2 LDS.32,
// bank-conflict-free (word = 12*r + cq covers all 32 banks over a warp).
template<int N, int K, bool AHALF>
__device__ __forceinline__ void mma_gemm(const void* __restrict__ Av,
                                         const float* __restrict__ Bg,
                                         __half* __restrict__ C, int M) {
    constexpr int BM = 128, BN = 64, BK = 16;
    constexpr int STR = 24;      // halves; 48B rows
    constexpr int NT = K / BK;
    __shared__ __half As[2][BM * STR];
    __shared__ __half Bs[2][BN * STR];

    const int tid  = threadIdx.x;
    const int lane = tid & 31, wid = tid >> 5;
    const int wm = wid & 3, wn = wid >> 2;
    const int r = lane >> 2, cq = lane & 3;
    const int row0 = blockIdx.y * BM;
    const int col0 = blockIdx.x * BN;

    // A staging: 128 rows x 16 k halves; thread -> row=tid>>1, seg=(tid&1)*8
    const int ahr = tid >> 1, ahk = (tid & 1) << 3;
    // B staging: 16k x 64n fp32 tile, transposed into Bs[n][k]
    const int bkk = tid & 15, bnn = (tid >> 4) << 2;

    const float*  Af = (const float*)Av;
    const __half* Ah = (const __half*)Av;

    auto stageA = [&](int buf, int k0) {
        __half2 hv[4];
        if (AHALF) {
            uint4 raw = make_uint4(0, 0, 0, 0);
            if (row0 + ahr < M)
                raw = *(const uint4*)(Ah + (size_t)(row0 + ahr) * K + k0 + ahk);
            *(uint4*)hv = raw;
        } else {
            float4 f0 = make_float4(0.f, 0.f, 0.f, 0.f), f1 = f0;
            if (row0 + ahr < M) {
                f0 = *(const float4*)(Af + (size_t)(row0 + ahr) * K + k0 + ahk);
                f1 = *(const float4*)(Af + (size_t)(row0 + ahr) * K + k0 + ahk + 4);
            }
            hv[0] = __floats2half2_rn(f0.x, f0.y);
            hv[1] = __floats2half2_rn(f0.z, f0.w);
            hv[2] = __floats2half2_rn(f1.x, f1.y);
            hv[3] = __floats2half2_rn(f1.z, f1.w);
        }
        *(uint4*)&As[buf][ahr * STR + ahk] = *(uint4*)hv;
    };
    auto stageB = [&](int buf, int k0) {
        float4 bv = *(const float4*)(Bg + (size_t)(k0 + bkk) * N + col0 + bnn);
        Bs[buf][(bnn + 0) * STR + bkk] = __float2half_rn(bv.x);
        Bs[buf][(bnn + 1) * STR + bkk] = __float2half_rn(bv.y);
        Bs[buf][(bnn + 2) * STR + bkk] = __float2half_rn(bv.z);
        Bs[buf][(bnn + 3) * STR + bkk] = __float2half_rn(bv.w);
    };

    float acc[2][4][4];
#pragma unroll
    for (int mt = 0; mt < 2; mt++)
#pragma unroll
        for (int nt = 0; nt < 4; nt++)
#pragma unroll
            for (int i = 0; i < 4; i++) acc[mt][nt][i] = 0.f;

    stageA(0, 0);
    stageB(0, 0);
    __syncthreads();

#pragma unroll 1
    for (int it = 0; it < NT; it++) {
        const int buf = it & 1;

        unsigned a[2][4], b[4][2];
#pragma unroll
        for (int mt = 0; mt < 2; mt++) {
            const int mb = wm * 32 + mt * 16 + r;
            const __half* ap = &As[buf][0];
            a[mt][0] = *(const unsigned*)(ap + (mb)     * STR + 2 * cq);
            a[mt][1] = *(const unsigned*)(ap + (mb + 8) * STR + 2 * cq);
            a[mt][2] = *(const unsigned*)(ap + (mb)     * STR + 2 * cq + 8);
            a[mt][3] = *(const unsigned*)(ap + (mb + 8) * STR + 2 * cq + 8);
        }
#pragma unroll
        for (int nt = 0; nt < 4; nt++) {
            const int nb = wn * 32 + nt * 8 + r;
            const __half* bp = &Bs[buf][0];
            b[nt][0] = *(const unsigned*)(bp + nb * STR + 2 * cq);
            b[nt][1] = *(const unsigned*)(bp + nb * STR + 2 * cq + 8);
        }
#pragma unroll
        for (int mt = 0; mt < 2; mt++)
#pragma unroll
            for (int nt = 0; nt < 4; nt++)
                mma_f16(acc[mt][nt], a[mt], b[nt]);

        if (it + 1 < NT) {
            stageA(buf ^ 1, (it + 1) * BK);
            stageB(buf ^ 1, (it + 1) * BK);
        }
        __syncthreads();
    }

    // epilogue: store fp16
#pragma unroll
    for (int mt = 0; mt < 2; mt++) {
        const int m_lo = row0 + wm * 32 + mt * 16 + r;
        const int m_hi = m_lo + 8;
#pragma unroll
        for (int nt = 0; nt < 4; nt++) {
            const int n = col0 + wn * 32 + nt * 8 + cq * 2;
            if (m_lo < M)
                *(__half2*)(C + (size_t)m_lo * N + n) =
                    __floats2half2_rn(acc[mt][nt][0], acc[mt][nt][1]);
            if (m_hi < M)
                *(__half2*)(C + (size_t)m_hi * N + n) =
                    __floats2half2_rn(acc[mt][nt][2], acc[mt][nt][3]);
        }
    }
}

__global__ void __launch_bounds__(256) k_gemm1(const float* __restrict__ A,
                                               const float* __restrict__ B) {
    mma_gemm<D1, INDIM, false>(A, B, g_h1h, NN);
}
__global__ void __launch_bounds__(256) k_gemm2(const float* __restrict__ B) {
    mma_gemm<HD, D1, true>(g_g1h, B, g_h2h, NN);
}

// ---------------- attention coefficient dots (read fp16 h) ----------------
__global__ void k_alpha1(const float* __restrict__ a_src1, const float* __restrict__ a_dst1) {
    int t = blockIdx.x * blockDim.x + threadIdx.x;
    if (t >= NN * HEADS) return;
    int n = t >> 2, h = t & 3;
    const uint4* hp = (const uint4*)(g_h1h + (size_t)n * D1 + h * HD);
    const float* sp = a_src1 + h * HD;
    const float* dp = a_dst1 + h * HD;
    float ss = 0.f, dd = 0.f;
#pragma unroll
    for (int i = 0; i < HD / 8; i++) {
        uint4 hv = hp[i];
        const __half2* h2 = (const __half2*)&hv;
#pragma unroll
        for (int j = 0; j < 4; j++) {
            float2 f = __half22float2(h2[j]);
            ss += f.x * sp[i * 8 + 2 * j] + f.y * sp[i * 8 + 2 * j + 1];
            dd += f.x * dp[i * 8 + 2 * j] + f.y * dp[i * 8 + 2 * j + 1];
        }
    }
    g_as1[t] = ss;
    g_ad1[t] = dd;
}

__global__ void k_alpha2(const float* __restrict__ a_src2, const float* __restrict__ a_dst2) {
    int n = blockIdx.x * blockDim.x + threadIdx.x;
    if (n >= NN) return;
    const uint4* hp = (const uint4*)(g_h2h + (size_t)n * HD);
    float ss = 0.f, dd = 0.f;
#pragma unroll
    for (int i = 0; i < HD / 8; i++) {
        uint4 hv = hp[i];
        const __half2* h2 = (const __half2*)&hv;
#pragma unroll
        for (int j = 0; j < 4; j++) {
            float2 f = __half22float2(h2[j]);
            ss += f.x * a_src2[i * 8 + 2 * j] + f.y * a_src2[i * 8 + 2 * j + 1];
            dd += f.x * a_dst2[i * 8 + 2 * j] + f.y * a_dst2[i * 8 + 2 * j + 1];
        }
    }
    g_as2[n] = ss;
    g_ad2[n] = dd;
}

// ---------------- CSR build (counting sort by dst) ----------------
__global__ void k_deg_init() {
    int i = blockIdx.x * blockDim.x + threadIdx.x;
    if (i < NN) g_deg[i] = 1;   // self-loop pre-counted
}
__global__ void k_hist(const int* __restrict__ dst) {
    int i = blockIdx.x * blockDim.x + threadIdx.x;
    if (i < EE) atomicAdd(&g_deg[dst[i]], 1);
}

#define SCAN_B 512
#define SCAN_NB ((NN + SCAN_B - 1) / SCAN_B)   // 196

__global__ void k_scan1() {
    __shared__ int sm[SCAN_B];
    int i = blockIdx.x * SCAN_B + threadIdx.x;
    int v = (i < NN) ? g_deg[i] : 0;
    sm[threadIdx.x] = v;
    __syncthreads();
    for (int off = 1; off < SCAN_B; off <<= 1) {
        int t = (threadIdx.x >= off) ? sm[threadIdx.x - off] : 0;
        __syncthreads();
        sm[threadIdx.x] += t;
        __syncthreads();
    }
    if (i < NN) g_rowptr[i] = sm[threadIdx.x] - v;
    if (threadIdx.x == SCAN_B - 1) g_blksums[blockIdx.x] = sm[threadIdx.x];
}
__global__ void k_scan2() {
    __shared__ int sm[256];
    int v = (threadIdx.x < SCAN_NB) ? g_blksums[threadIdx.x] : 0;
    sm[threadIdx.x] = v;
    __syncthreads();
    for (int off = 1; off < 256; off <<= 1) {
        int t = (threadIdx.x >= off) ? sm[threadIdx.x - off] : 0;
        __syncthreads();
        sm[threadIdx.x] += t;
        __syncthreads();
    }
    g_blksums[threadIdx.x] = sm[threadIdx.x] - v;
}
__global__ void k_scan3() {
    int i = blockIdx.x * blockDim.x + threadIdx.x;
    if (i < NN) {
        int r = g_rowptr[i] + g_blksums[i / SCAN_B];
        g_rowptr[i] = r;
        g_cursor[i] = r;
    } else if (i == NN) {
        g_rowptr[NN] = ET;
    }
}
__global__ void k_scatter(const int* __restrict__ ei) {
    int i = blockIdx.x * blockDim.x + threadIdx.x;
    if (i >= ET) return;
    int s, d;
    if (i < EE) { s = ei[i]; d = ei[EE + i]; }
    else        { s = d = i - EE; }
    int pos = atomicAdd(&g_cursor[d], 1);
    g_srcs[pos] = s;
}

// ---------------- layer-1 aggregation: one warp per dst node ----------------
__global__ void k_agg1(const float* __restrict__ b1) {
    int gw = (blockIdx.x * blockDim.x + threadIdx.x) >> 5;
    if (gw >= NN) return;
    const int lane = threadIdx.x & 31;
    const int v = gw;
    const int r0 = g_rowptr[v], r1 = g_rowptr[v + 1];
    const float4 adv = ((const float4*)g_ad1)[v];

    // pass 1 (online softmax stats, lane-parallel over edges)
    float mx0 = -1e30f, mx1 = -1e30f, mx2 = -1e30f, mx3 = -1e30f;
    float s0 = 0.f, s1 = 0.f, s2 = 0.f, s3 = 0.f;
    for (int e = r0 + lane; e < r1; e += 32) {
        int s = g_srcs[e];
        float4 as = ((const float4*)g_as1)[s];
        float w0 = lrelu(as.x + adv.x);
        float w1 = lrelu(as.y + adv.y);
        float w2 = lrelu(as.z + adv.z);
        float w3 = lrelu(as.w + adv.w);
        float n0 = fmaxf(mx0, w0), n1 = fmaxf(mx1, w1);
        float n2 = fmaxf(mx2, w2), n3 = fmaxf(mx3, w3);
        s0 = s0 * __expf(mx0 - n0) + __expf(w0 - n0);
        s1 = s1 * __expf(mx1 - n1) + __expf(w1 - n1);
        s2 = s2 * __expf(mx2 - n2) + __expf(w2 - n2);
        s3 = s3 * __expf(mx3 - n3) + __expf(w3 - n3);
        mx0 = n0; mx1 = n1; mx2 = n2; mx3 = n3;
    }
#pragma unroll
    for (int o = 16; o; o >>= 1) {
        float om, os, nm;
        om = __shfl_xor_sync(0xffffffffu, mx0, o); os = __shfl_xor_sync(0xffffffffu, s0, o);
        nm = fmaxf(mx0, om); s0 = s0 * __expf(mx0 - nm) + os * __expf(om - nm); mx0 = nm;
        om = __shfl_xor_sync(0xffffffffu, mx1, o); os = __shfl_xor_sync(0xffffffffu, s1, o);
        nm = fmaxf(mx1, om); s1 = s1 * __expf(mx1 - nm) + os * __expf(om - nm); mx1 = nm;
        om = __shfl_xor_sync(0xffffffffu, mx2, o); os = __shfl_xor_sync(0xffffffffu, s2, o);
        nm = fmaxf(mx2, om); s2 = s2 * __expf(mx2 - nm) + os * __expf(om - nm); mx2 = nm;
        om = __shfl_xor_sync(0xffffffffu, mx3, o); os = __shfl_xor_sync(0xffffffffu, s3, o);
        nm = fmaxf(mx3, om); s3 = s3 * __expf(mx3 - nm) + os * __expf(om - nm); mx3 = nm;
    }

    // pass 2: weighted aggregation, unrolled x4 for MLP.
    // lane owns 8 contiguous elems = slice of one head.
    const int head = lane >> 3;
    const float adh = head == 0 ? adv.x : head == 1 ? adv.y : head == 2 ? adv.z : adv.w;
    const float mh  = head == 0 ? mx0  : head == 1 ? mx1  : head == 2 ? mx2  : mx3;
    const float sh  = head == 0 ? s0   : head == 1 ? s1   : head == 2 ? s2   : s3;
    const float ih  = 1.f / sh;
    const float* asb = g_as1 + head;

    float acc[8];
#pragma unroll
    for (int i = 0; i < 8; i++) acc[i] = 0.f;

    const __half* h1b = g_h1h + lane * 8;
    int e = r0;
    for (; e + 4 <= r1; e += 4) {
        int sa = g_srcs[e], sb = g_srcs[e + 1], sc = g_srcs[e + 2], sd = g_srcs[e + 3];
        float wa = asb[sa * 4], wb = asb[sb * 4], wc = asb[sc * 4], wd = asb[sd * 4];
        uint4 ha = *(const uint4*)(h1b + (size_t)sa * D1);
        uint4 hb = *(const uint4*)(h1b + (size_t)sb * D1);
        uint4 hc = *(const uint4*)(h1b + (size_t)sc * D1);
        uint4 hd = *(const uint4*)(h1b + (size_t)sd * D1);
        float aa = __expf(lrelu(wa + adh) - mh) * ih;
        float ab = __expf(lrelu(wb + adh) - mh) * ih;
        float ac = __expf(lrelu(wc + adh) - mh) * ih;
        float ad = __expf(lrelu(wd + adh) - mh) * ih;
        const __half2* pa = (const __half2*)&ha;
        const __half2* pb = (const __half2*)&hb;
        const __half2* pc = (const __half2*)&hc;
        const __half2* pd = (const __half2*)&hd;
#pragma unroll
        for (int j = 0; j < 4; j++) {
            float2 fa = __half22float2(pa[j]);
            float2 fb = __half22float2(pb[j]);
            float2 fc = __half22float2(pc[j]);
            float2 fd = __half22float2(pd[j]);
            acc[2 * j]     = fmaf(fa.x, aa, fmaf(fb.x, ab, fmaf(fc.x, ac, fmaf(fd.x, ad, acc[2 * j]))));
            acc[2 * j + 1] = fmaf(fa.y, aa, fmaf(fb.y, ab, fmaf(fc.y, ac, fmaf(fd.y, ad, acc[2 * j + 1]))));
        }
    }
    for (; e < r1; e++) {
        int s = g_srcs[e];
        float a = __expf(lrelu(asb[s * 4] + adh) - mh) * ih;
        uint4 hv = *(const uint4*)(h1b + (size_t)s * D1);
        const __half2* h2 = (const __half2*)&hv;
#pragma unroll
        for (int j = 0; j < 4; j++) {
            float2 f = __half22float2(h2[j]);
            acc[2 * j]     = fmaf(f.x, a, acc[2 * j]);
            acc[2 * j + 1] = fmaf(f.y, a, acc[2 * j + 1]);
        }
    }

    // epilogue: +b1, ELU, store fp16 (single 16B store)
    const float* bb = b1 + lane * 8;
    __half2 oh[4];
#pragma unroll
    for (int j = 0; j < 4; j++)
        oh[j] = __floats2half2_rn(eluf(acc[2 * j] + bb[2 * j]),
                                  eluf(acc[2 * j + 1] + bb[2 * j + 1]));
    *(uint4*)(g_g1h + (size_t)v * D1 + lane * 8) = *(uint4*)oh;
}

// ---------------- layer-2 aggregation + ELU + final linear ----------------
__global__ void k_agg2(const float* __restrict__ b2, const float* __restrict__ lw,
                       const float* __restrict__ lb, float* __restrict__ out) {
    int gw = (blockIdx.x * blockDim.x + threadIdx.x) >> 5;
    if (gw >= NN) return;
    const int lane = threadIdx.x & 31;
    const int v = gw;
    const int r0 = g_rowptr[v], r1 = g_rowptr[v + 1];
    const float adv = g_ad2[v];

    float mx = -1e30f, sm = 0.f;
    for (int e = r0 + lane; e < r1; e += 32) {
        float w = lrelu(g_as2[g_srcs[e]] + adv);
        float nm = fmaxf(mx, w);
        sm = sm * __expf(mx - nm) + __expf(w - nm);
        mx = nm;
    }
#pragma unroll
    for (int o = 16; o; o >>= 1) {
        float om = __shfl_xor_sync(0xffffffffu, mx, o);
        float os = __shfl_xor_sync(0xffffffffu, sm, o);
        float nm = fmaxf(mx, om);
        sm = sm * __expf(mx - nm) + os * __expf(om - nm);
        mx = nm;
    }
    const float inv = 1.f / sm;

    float2 acc = make_float2(0.f, 0.f);
    const __half* h2b = g_h2h + lane * 2;
    int e = r0;
    for (; e + 4 <= r1; e += 4) {
        int sa = g_srcs[e], sb = g_srcs[e + 1], sc = g_srcs[e + 2], sd = g_srcs[e + 3];
        float wa = g_as2[sa], wb = g_as2[sb], wc = g_as2[sc], wd = g_as2[sd];
        __half2 xa = *(const __half2*)(h2b + (size_t)sa * HD);
        __half2 xb = *(const __half2*)(h2b + (size_t)sb * HD);
        __half2 xc = *(const __half2*)(h2b + (size_t)sc * HD);
        __half2 xd = *(const __half2*)(h2b + (size_t)sd * HD);
        float aa = __expf(lrelu(wa + adv) - mx) * inv;
        float ab = __expf(lrelu(wb + adv) - mx) * inv;
        float ac = __expf(lrelu(wc + adv) - mx) * inv;
        float ad = __expf(lrelu(wd + adv) - mx) * inv;
        float2 fa = __half22float2(xa), fb = __half22float2(xb);
        float2 fc = __half22float2(xc), fd = __half22float2(xd);
        acc.x = fmaf(fa.x, aa, fmaf(fb.x, ab, fmaf(fc.x, ac, fmaf(fd.x, ad, acc.x))));
        acc.y = fmaf(fa.y, aa, fmaf(fb.y, ab, fmaf(fc.y, ac, fmaf(fd.y, ad, acc.y))));
    }
    for (; e < r1; e++) {
        int s = g_srcs[e];
        float a = __expf(lrelu(g_as2[s] + adv) - mx) * inv;
        float2 x = __half22float2(*(const __half2*)(h2b + (size_t)s * HD));
        acc.x = fmaf(x.x, a, acc.x);
        acc.y = fmaf(x.y, a, acc.y);
    }

    const int d = 2 * lane;
    float t0 = eluf(acc.x + b2[d]);
    float t1 = eluf(acc.y + b2[d + 1]);
    float y0 = t0 * lw[d * 2]     + t1 * lw[d * 2 + 2];
    float y1 = t0 * lw[d * 2 + 1] + t1 * lw[d * 2 + 3];
#pragma unroll
    for (int o = 16; o; o >>= 1) {
        y0 += __shfl_xor_sync(0xffffffffu, y0, o);
        y1 += __shfl_xor_sync(0xffffffffu, y1, o);
    }
    if (lane == 0) {
        out[2 * v]     = y0 + lb[0];
        out[2 * v + 1] = y1 + lb[1];
    }
}

// ---------------- launch ----------------
extern "C" void kernel_launch(void* const* d_in, const int* in_sizes, int n_in,
                              void* d_out, int out_size) {
    const float* x      = (const float*)d_in[0];
    const int*   ei     = (const int*)d_in[1];     // int32: jax default x64 disabled
    const float* W1     = (const float*)d_in[2];
    const float* a_src1 = (const float*)d_in[3];
    const float* a_dst1 = (const float*)d_in[4];
    const float* b1     = (const float*)d_in[5];
    const float* W2     = (const float*)d_in[6];
    const float* a_src2 = (const float*)d_in[7];
    const float* a_dst2 = (const float*)d_in[8];
    const float* b2     = (const float*)d_in[9];
    const float* lw     = (const float*)d_in[10];
    const float* lb     = (const float*)d_in[11];
    float*       out    = (float*)d_out;

    static cudaStream_t s1 = nullptr;
    static cudaEvent_t evRoot = nullptr, evCsr = nullptr;
    if (s1 == nullptr) {
        cudaStreamCreateWithFlags(&s1, cudaStreamNonBlocking);
        cudaEventCreateWithFlags(&evRoot, cudaEventDisableTiming);
        cudaEventCreateWithFlags(&evCsr, cudaEventDisableTiming);
    }

    // fork: CSR chain on s1, GEMM1 chain on the main stream
    cudaEventRecord(evRoot, 0);
    cudaStreamWaitEvent(s1, evRoot, 0);

    k_deg_init<<<(NN + 255) / 256, 256, 0, s1>>>();
    k_hist<<<(EE + 255) / 256, 256, 0, s1>>>(ei + EE);
    k_scan1<<<SCAN_NB, SCAN_B, 0, s1>>>();

    k_gemm1<<<dim3(D1 / 64, (NN + 127) / 128), 256>>>(x, W1);

    k_scan2<<<1, 256, 0, s1>>>();
    k_scan3<<<(NN + 1 + 255) / 256, 256, 0, s1>>>();
    k_scatter<<<(ET + 255) / 256, 256, 0, s1>>>(ei);
    cudaEventRecord(evCsr, s1);

    k_alpha1<<<(NN * HEADS + 255) / 256, 256>>>(a_src1, a_dst1);

    cudaStreamWaitEvent(0, evCsr, 0);
    k_agg1<<<(NN + 7) / 8, 256>>>(b1);

    // layer 2
    k_gemm2<<<dim3(1, (NN + 127) / 128), 256>>>(W2);
    k_alpha2<<<(NN + 255) / 256, 256>>>(a_src2, a_dst2);
    k_agg2<<<(NN + 7) / 8, 256>>>(b2, lw, lb, out);
}

// round 7
// speedup vs baseline: 1.9739x; 1.2140x over previous
#include <cuda_runtime.h>
#include <cuda_fp16.h>
#include <cstdint>

#define NN 100000
#define EE 3200000
#define ET (EE + NN)           // 3,300,000 edges incl. self loops
#define HEADS 4
#define HD 64
#define D1 256                 // HEADS*HD
#define INDIM 128

// ---------------- scratch (static device globals; no allocs) ----------------
__device__ __half g_h1h[(size_t)NN * D1];   // layer1 h (fp16)            (51.2 MB)
__device__ __half g_g1h[(size_t)NN * D1];   // elu(agg1+b1) (fp16)        (51.2 MB)
__device__ __half g_h2h[(size_t)NN * HD];   // layer2 h (fp16)            (12.8 MB)
__device__ float g_as1[NN * HEADS];
__device__ float g_ad1[NN * HEADS];
__device__ float g_as2[NN];
__device__ float g_ad2[NN];
__device__ int   g_deg[NN];                 // zero at entry of every launch
__device__ int   g_rowptr[NN + 1];
__device__ int   g_cursor[NN];
__device__ int   g_blksums[256];
__device__ int   g_srcs[ET];                // CSR-by-dst src indices (13.2 MB)

__device__ __forceinline__ float lrelu(float x) { return fmaxf(x, 0.2f * x); }
__device__ __forceinline__ float eluf(float x)  { return x > 0.f ? x : expm1f(x); }

#define SM_OFF 8.0f   // constant softmax offset (exact in ratio; avoids overflow)

__device__ __forceinline__ void mma_f16(float* d, const unsigned* a, const unsigned* b) {
    asm volatile(
        "mma.sync.aligned.m16n8k16.row.col.f32.f16.f16.f32 "
        "{%0,%1,%2,%3}, {%4,%5,%6,%7}, {%8,%9}, {%0,%1,%2,%3};\n"
        : "+f"(d[0]), "+f"(d[1]), "+f"(d[2]), "+f"(d[3])
        : "r"(a[0]), "r"(a[1]), "r"(a[2]), "r"(a[3]), "r"(b[0]), "r"(b[1]));
}

// ---------------- fp16 tensor-core GEMM: BM=128, BN=64, BK=16 ----------------
// 8 warps (4m x 2n); warp = 2x4 m16n8k16 tiles. Fused alpha epilogue: since
// BN == HD, each column-block is one attention head; per-row dots with
// a_src/a_dst are reduced from the fp32 accumulators.
template<int N, int K, bool AHALF, int SSTR>
__device__ __forceinline__ void mma_gemm(const void* __restrict__ Av,
                                         const float* __restrict__ Bg,
                                         __half* __restrict__ C, int M,
                                         const float* __restrict__ av,
                                         const float* __restrict__ dv,
                                         float* __restrict__ sOut,
                                         float* __restrict__ dOut) {
    constexpr int BM = 128, BN = 64, BK = 16;
    constexpr int STR = 24;      // halves; 48B rows
    constexpr int NT = K / BK;
    __shared__ __half As[2][BM * STR];
    __shared__ __half Bs[2][BN * STR];
    __shared__ float red_s[BM], red_d[BM];

    const int tid  = threadIdx.x;
    const int lane = tid & 31, wid = tid >> 5;
    const int wm = wid & 3, wn = wid >> 2;
    const int r = lane >> 2, cq = lane & 3;
    const int row0 = blockIdx.y * BM;
    const int col0 = blockIdx.x * BN;

    const int ahr = tid >> 1, ahk = (tid & 1) << 3;
    const int bkk = tid & 15, bnn = (tid >> 4) << 2;

    const float*  Af = (const float*)Av;
    const __half* Ah = (const __half*)Av;

    auto stageA = [&](int buf, int k0) {
        __half2 hv[4];
        if (AHALF) {
            uint4 raw = make_uint4(0, 0, 0, 0);
            if (row0 + ahr < M)
                raw = *(const uint4*)(Ah + (size_t)(row0 + ahr) * K + k0 + ahk);
            *(uint4*)hv = raw;
        } else {
            float4 f0 = make_float4(0.f, 0.f, 0.f, 0.f), f1 = f0;
            if (row0 + ahr < M) {
                f0 = *(const float4*)(Af + (size_t)(row0 + ahr) * K + k0 + ahk);
                f1 = *(const float4*)(Af + (size_t)(row0 + ahr) * K + k0 + ahk + 4);
            }
            hv[0] = __floats2half2_rn(f0.x, f0.y);
            hv[1] = __floats2half2_rn(f0.z, f0.w);
            hv[2] = __floats2half2_rn(f1.x, f1.y);
            hv[3] = __floats2half2_rn(f1.z, f1.w);
        }
        *(uint4*)&As[buf][ahr * STR + ahk] = *(uint4*)hv;
    };
    auto stageB = [&](int buf, int k0) {
        float4 bv = *(const float4*)(Bg + (size_t)(k0 + bkk) * N + col0 + bnn);
        Bs[buf][(bnn + 0) * STR + bkk] = __float2half_rn(bv.x);
        Bs[buf][(bnn + 1) * STR + bkk] = __float2half_rn(bv.y);
        Bs[buf][(bnn + 2) * STR + bkk] = __float2half_rn(bv.z);
        Bs[buf][(bnn + 3) * STR + bkk] = __float2half_rn(bv.w);
    };

    float acc[2][4][4];
#pragma unroll
    for (int mt = 0; mt < 2; mt++)
#pragma unroll
        for (int nt = 0; nt < 4; nt++)
#pragma unroll
            for (int i = 0; i < 4; i++) acc[mt][nt][i] = 0.f;

    stageA(0, 0);
    stageB(0, 0);
    __syncthreads();

#pragma unroll 1
    for (int it = 0; it < NT; it++) {
        const int buf = it & 1;

        unsigned a[2][4], b[4][2];
#pragma unroll
        for (int mt = 0; mt < 2; mt++) {
            const int mb = wm * 32 + mt * 16 + r;
            const __half* ap = &As[buf][0];
            a[mt][0] = *(const unsigned*)(ap + (mb)     * STR + 2 * cq);
            a[mt][1] = *(const unsigned*)(ap + (mb + 8) * STR + 2 * cq);
            a[mt][2] = *(const unsigned*)(ap + (mb)     * STR + 2 * cq + 8);
            a[mt][3] = *(const unsigned*)(ap + (mb + 8) * STR + 2 * cq + 8);
        }
#pragma unroll
        for (int nt = 0; nt < 4; nt++) {
            const int nb = wn * 32 + nt * 8 + r;
            const __half* bp = &Bs[buf][0];
            b[nt][0] = *(const unsigned*)(bp + nb * STR + 2 * cq);
            b[nt][1] = *(const unsigned*)(bp + nb * STR + 2 * cq + 8);
        }
#pragma unroll
        for (int mt = 0; mt < 2; mt++)
#pragma unroll
            for (int nt = 0; nt < 4; nt++)
                mma_f16(acc[mt][nt], a[mt], b[nt]);

        if (it + 1 < NT) {
            stageA(buf ^ 1, (it + 1) * BK);
            stageB(buf ^ 1, (it + 1) * BK);
        }
        __syncthreads();
    }

    // epilogue: store fp16 C
#pragma unroll
    for (int mt = 0; mt < 2; mt++) {
        const int m_lo = row0 + wm * 32 + mt * 16 + r;
        const int m_hi = m_lo + 8;
#pragma unroll
        for (int nt = 0; nt < 4; nt++) {
            const int n = col0 + wn * 32 + nt * 8 + cq * 2;
            if (m_lo < M)
                *(__half2*)(C + (size_t)m_lo * N + n) =
                    __floats2half2_rn(acc[mt][nt][0], acc[mt][nt][1]);
            if (m_hi < M)
                *(__half2*)(C + (size_t)m_hi * N + n) =
                    __floats2half2_rn(acc[mt][nt][2], acc[mt][nt][3]);
        }
    }

    // fused alpha epilogue: ss/dd per row from fp32 accumulators
    if (tid < BM) { red_s[tid] = 0.f; red_d[tid] = 0.f; }
    __syncthreads();

    float ps0[2] = {0.f, 0.f}, ps1[2] = {0.f, 0.f};
    float pd0[2] = {0.f, 0.f}, pd1[2] = {0.f, 0.f};
#pragma unroll
    for (int nt = 0; nt < 4; nt++) {
#pragma unroll
        for (int j = 0; j < 2; j++) {
            const int c = wn * 32 + nt * 8 + cq * 2 + j;
            const float a_ = av[c], d_ = dv[c];
#pragma unroll
            for (int mt = 0; mt < 2; mt++) {
                ps0[mt] = fmaf(acc[mt][nt][j],     a_, ps0[mt]);
                pd0[mt] = fmaf(acc[mt][nt][j],     d_, pd0[mt]);
                ps1[mt] = fmaf(acc[mt][nt][2 + j], a_, ps1[mt]);
                pd1[mt] = fmaf(acc[mt][nt][2 + j], d_, pd1[mt]);
            }
        }
    }
#pragma unroll
    for (int o = 1; o <= 2; o <<= 1) {
#pragma unroll
        for (int mt = 0; mt < 2; mt++) {
            ps0[mt] += __shfl_xor_sync(0xffffffffu, ps0[mt], o);
            ps1[mt] += __shfl_xor_sync(0xffffffffu, ps1[mt], o);
            pd0[mt] += __shfl_xor_sync(0xffffffffu, pd0[mt], o);
            pd1[mt] += __shfl_xor_sync(0xffffffffu, pd1[mt], o);
        }
    }
    if (cq == 0) {
#pragma unroll
        for (int mt = 0; mt < 2; mt++) {
            const int lr = wm * 32 + mt * 16 + r;
            atomicAdd(&red_s[lr],     ps0[mt]);
            atomicAdd(&red_s[lr + 8], ps1[mt]);
            atomicAdd(&red_d[lr],     pd0[mt]);
            atomicAdd(&red_d[lr + 8], pd1[mt]);
        }
    }
    __syncthreads();
    if (tid < BM) {
        const int row = row0 + tid;
        if (row < M) {
            sOut[(size_t)row * SSTR] = red_s[tid];
            dOut[(size_t)row * SSTR] = red_d[tid];
        }
    }
}

__global__ void __launch_bounds__(256) k_gemm1(const float* __restrict__ A,
                                               const float* __restrict__ B,
                                               const float* __restrict__ asrc,
                                               const float* __restrict__ adst) {
    mma_gemm<D1, INDIM, false, HEADS>(A, B, g_h1h, NN,
                                      asrc + blockIdx.x * HD, adst + blockIdx.x * HD,
                                      g_as1 + blockIdx.x, g_ad1 + blockIdx.x);
}
__global__ void __launch_bounds__(256) k_gemm2(const float* __restrict__ B,
                                               const float* __restrict__ asrc,
                                               const float* __restrict__ adst) {
    mma_gemm<HD, D1, true, 1>(g_g1h, B, g_h2h, NN, asrc, adst, g_as2, g_ad2);
}

// ---------------- CSR build (counting sort by dst) ----------------
__global__ void k_hist(const int* __restrict__ dst) {
    int i = blockIdx.x * blockDim.x + threadIdx.x;
    if (i < EE) atomicAdd(&g_deg[dst[i]], 1);
}

#define SCAN_B 512
#define SCAN_NB ((NN + SCAN_B - 1) / SCAN_B)   // 196

__global__ void k_scan1() {
    __shared__ int sm[SCAN_B];
    int i = blockIdx.x * SCAN_B + threadIdx.x;
    int v = (i < NN) ? g_deg[i] + 1 : 0;       // +1 = self-loop
    sm[threadIdx.x] = v;
    __syncthreads();
    for (int off = 1; off < SCAN_B; off <<= 1) {
        int t = (threadIdx.x >= off) ? sm[threadIdx.x - off] : 0;
        __syncthreads();
        sm[threadIdx.x] += t;
        __syncthreads();
    }
    if (i < NN) g_rowptr[i] = sm[threadIdx.x] - v;
    if (threadIdx.x == SCAN_B - 1) g_blksums[blockIdx.x] = sm[threadIdx.x];
}
// merged scan2+scan3: every block redundantly scans the 196 block sums
__global__ void k_scan3() {
    __shared__ int sm[256], sme[256];
    const int t = threadIdx.x;
    int v = (t < SCAN_NB) ? g_blksums[t] : 0;
    sm[t] = v;
    __syncthreads();
    for (int off = 1; off < 256; off <<= 1) {
        int x = (t >= off) ? sm[t - off] : 0;
        __syncthreads();
        sm[t] += x;
        __syncthreads();
    }
    sme[t] = sm[t] - v;                         // exclusive
    __syncthreads();
    int i = blockIdx.x * blockDim.x + t;
    if (i < NN) {
        int r = g_rowptr[i] + sme[i / SCAN_B];
        g_rowptr[i] = r;
        g_cursor[i] = r;
        g_deg[i] = 0;                           // re-zero for next launch's hist
    } else if (i == NN) {
        g_rowptr[NN] = ET;
    }
}
__global__ void k_scatter(const int* __restrict__ ei) {
    int i = blockIdx.x * blockDim.x + threadIdx.x;
    if (i >= ET) return;
    int s, d;
    if (i < EE) { s = ei[i]; d = ei[EE + i]; }
    else        { s = d = i - EE; }
    int pos = atomicAdd(&g_cursor[d], 1);
    g_srcs[pos] = s;
}

// ------- layer-1 aggregation: one warp per dst node, single pass -------
// Offset-softmax: alpha = exp(e-8)/S, S = sum exp(e-8). No max pass needed.
__global__ void k_agg1(const float* __restrict__ b1) {
    int gw = (blockIdx.x * blockDim.x + threadIdx.x) >> 5;
    if (gw >= NN) return;
    const int lane = threadIdx.x & 31;
    const int v = gw;
    const int r0 = g_rowptr[v], r1 = g_rowptr[v + 1];
    const float4 adv = ((const float4*)g_ad1)[v];

    const int head = lane >> 3;                // 8 lanes per head
    const float adh = head == 0 ? adv.x : head == 1 ? adv.y : head == 2 ? adv.z : adv.w;
    const float* asb = g_as1 + head;

    float S = 0.f;
    float acc[8];
#pragma unroll
    for (int i = 0; i < 8; i++) acc[i] = 0.f;

    const __half* h1b = g_h1h + lane * 8;
    int e = r0;
    for (; e + 4 <= r1; e += 4) {
        int sa = g_srcs[e], sb = g_srcs[e + 1], sc = g_srcs[e + 2], sd = g_srcs[e + 3];
        float wa = asb[sa * 4], wb = asb[sb * 4], wc = asb[sc * 4], wd = asb[sd * 4];
        uint4 ha = *(const uint4*)(h1b + (size_t)sa * D1);
        uint4 hb = *(const uint4*)(h1b + (size_t)sb * D1);
        uint4 hc = *(const uint4*)(h1b + (size_t)sc * D1);
        uint4 hd = *(const uint4*)(h1b + (size_t)sd * D1);
        float aa = __expf(lrelu(wa + adh) - SM_OFF);
        float ab = __expf(lrelu(wb + adh) - SM_OFF);
        float ac = __expf(lrelu(wc + adh) - SM_OFF);
        float ad = __expf(lrelu(wd + adh) - SM_OFF);
        S += (aa + ab) + (ac + ad);
        const __half2* pa = (const __half2*)&ha;
        const __half2* pb = (const __half2*)&hb;
        const __half2* pc = (const __half2*)&hc;
        const __half2* pd = (const __half2*)&hd;
#pragma unroll
        for (int j = 0; j < 4; j++) {
            float2 fa = __half22float2(pa[j]);
            float2 fb = __half22float2(pb[j]);
            float2 fc = __half22float2(pc[j]);
            float2 fd = __half22float2(pd[j]);
            acc[2 * j]     = fmaf(fa.x, aa, fmaf(fb.x, ab, fmaf(fc.x, ac, fmaf(fd.x, ad, acc[2 * j]))));
            acc[2 * j + 1] = fmaf(fa.y, aa, fmaf(fb.y, ab, fmaf(fc.y, ac, fmaf(fd.y, ad, acc[2 * j + 1]))));
        }
    }
    for (; e < r1; e++) {
        int s = g_srcs[e];
        float a = __expf(lrelu(asb[s * 4] + adh) - SM_OFF);
        S += a;
        uint4 hv = *(const uint4*)(h1b + (size_t)s * D1);
        const __half2* h2 = (const __half2*)&hv;
#pragma unroll
        for (int j = 0; j < 4; j++) {
            float2 f = __half22float2(h2[j]);
            acc[2 * j]     = fmaf(f.x, a, acc[2 * j]);
            acc[2 * j + 1] = fmaf(f.y, a, acc[2 * j + 1]);
        }
    }

    const float inv = 1.f / S;
    const float* bb = b1 + lane * 8;
    __half2 oh[4];
#pragma unroll
    for (int j = 0; j < 4; j++)
        oh[j] = __floats2half2_rn(eluf(fmaf(acc[2 * j], inv, bb[2 * j])),
                                  eluf(fmaf(acc[2 * j + 1], inv, bb[2 * j + 1])));
    *(uint4*)(g_g1h + (size_t)v * D1 + lane * 8) = *(uint4*)oh;
}

// ------- layer-2 aggregation + ELU + final linear, single pass -------
__global__ void k_agg2(const float* __restrict__ b2, const float* __restrict__ lw,
                       const float* __restrict__ lb, float* __restrict__ out) {
    int gw = (blockIdx.x * blockDim.x + threadIdx.x) >> 5;
    if (gw >= NN) return;
    const int lane = threadIdx.x & 31;
    const int v = gw;
    const int r0 = g_rowptr[v], r1 = g_rowptr[v + 1];
    const float adv = g_ad2[v];

    float S = 0.f;
    float2 acc = make_float2(0.f, 0.f);
    const __half* h2b = g_h2h + lane * 2;
    int e = r0;
    for (; e + 4 <= r1; e += 4) {
        int sa = g_srcs[e], sb = g_srcs[e + 1], sc = g_srcs[e + 2], sd = g_srcs[e + 3];
        float wa = g_as2[sa], wb = g_as2[sb], wc = g_as2[sc], wd = g_as2[sd];
        __half2 xa = *(const __half2*)(h2b + (size_t)sa * HD);
        __half2 xb = *(const __half2*)(h2b + (size_t)sb * HD);
        __half2 xc = *(const __half2*)(h2b + (size_t)sc * HD);
        __half2 xd = *(const __half2*)(h2b + (size_t)sd * HD);
        float aa = __expf(lrelu(wa + adv) - SM_OFF);
        float ab = __expf(lrelu(wb + adv) - SM_OFF);
        float ac = __expf(lrelu(wc + adv) - SM_OFF);
        float ad = __expf(lrelu(wd + adv) - SM_OFF);
        S += (aa + ab) + (ac + ad);
        float2 fa = __half22float2(xa), fb = __half22float2(xb);
        float2 fc = __half22float2(xc), fd = __half22float2(xd);
        acc.x = fmaf(fa.x, aa, fmaf(fb.x, ab, fmaf(fc.x, ac, fmaf(fd.x, ad, acc.x))));
        acc.y = fmaf(fa.y, aa, fmaf(fb.y, ab, fmaf(fc.y, ac, fmaf(fd.y, ad, acc.y))));
    }
    for (; e < r1; e++) {
        int s = g_srcs[e];
        float a = __expf(lrelu(g_as2[s] + adv) - SM_OFF);
        S += a;
        float2 x = __half22float2(*(const __half2*)(h2b + (size_t)s * HD));
        acc.x = fmaf(x.x, a, acc.x);
        acc.y = fmaf(x.y, a, acc.y);
    }

    const float inv = 1.f / S;
    const int d = 2 * lane;
    float t0 = eluf(fmaf(acc.x, inv, b2[d]));
    float t1 = eluf(fmaf(acc.y, inv, b2[d + 1]));
    float y0 = t0 * lw[d * 2]     + t1 * lw[d * 2 + 2];
    float y1 = t0 * lw[d * 2 + 1] + t1 * lw[d * 2 + 3];
#pragma unroll
    for (int o = 16; o; o >>= 1) {
        y0 += __shfl_xor_sync(0xffffffffu, y0, o);
        y1 += __shfl_xor_sync(0xffffffffu, y1, o);
    }
    if (lane == 0) {
        out[2 * v]     = y0 + lb[0];
        out[2 * v + 1] = y1 + lb[1];
    }
}

// ---------------- launch ----------------
extern "C" void kernel_launch(void* const* d_in, const int* in_sizes, int n_in,
                              void* d_out, int out_size) {
    const float* x      = (const float*)d_in[0];
    const int*   ei     = (const int*)d_in[1];     // int32: jax default x64 disabled
    const float* W1     = (const float*)d_in[2];
    const float* a_src1 = (const float*)d_in[3];
    const float* a_dst1 = (const float*)d_in[4];
    const float* b1     = (const float*)d_in[5];
    const float* W2     = (const float*)d_in[6];
    const float* a_src2 = (const float*)d_in[7];
    const float* a_dst2 = (const float*)d_in[8];
    const float* b2     = (const float*)d_in[9];
    const float* lw     = (const float*)d_in[10];
    const float* lb     = (const float*)d_in[11];
    float*       out    = (float*)d_out;

    static cudaStream_t s1 = nullptr;
    static cudaEvent_t evRoot = nullptr, evCsr = nullptr;
    if (s1 == nullptr) {
        cudaStreamCreateWithFlags(&s1, cudaStreamNonBlocking);
        cudaEventCreateWithFlags(&evRoot, cudaEventDisableTiming);
        cudaEventCreateWithFlags(&evCsr, cudaEventDisableTiming);
    }

    // fork: CSR chain on s1, GEMM1 on main stream
    cudaEventRecord(evRoot, 0);
    cudaStreamWaitEvent(s1, evRoot, 0);

    k_hist<<<(EE + 255) / 256, 256, 0, s1>>>(ei + EE);          // #1
    k_scan1<<<SCAN_NB, SCAN_B, 0, s1>>>();                      // #2
    k_scan3<<<(NN + 1 + 255) / 256, 256, 0, s1>>>();            // #3

    k_gemm1<<<dim3(D1 / 64, (NN + 127) / 128), 256>>>(x, W1, a_src1, a_dst1);  // #4 (profiled)

    k_scatter<<<(ET + 255) / 256, 256, 0, s1>>>(ei);            // #5
    cudaEventRecord(evCsr, s1);

    // join: agg1 needs CSR + gemm1(+fused alphas)
    cudaStreamWaitEvent(0, evCsr, 0);
    k_agg1<<<(NN + 7) / 8, 256>>>(b1);                          // #6

    // layer 2
    k_gemm2<<<dim3(1, (NN + 127) / 128), 256>>>(W2, a_src2, a_dst2);  // #7
    k_agg2<<<(NN + 7) / 8, 256>>>(b2, lw, lb, out);             // #8
}